// round 1
// baseline (speedup 1.0000x reference)
#include <cuda_runtime.h>
#include <math.h>

#define B_  16
#define L_  1024
#define H_  512
#define KK_ 32
#define BL_ (B_ * L_)          // 16384

// ---------------- scratch (no allocations allowed) ----------------
__device__ float g_q[B_ * H_];
__device__ float g_k[BL_ * H_];
__device__ float g_v[BL_ * H_];
__device__ float g_s[B_ * L_];
__device__ float g_attn[BL_ * H_];
__device__ float g_x[BL_ * H_];
__device__ int   g_index[L_ * KK_];
__device__ int   g_is64;

// ---------------- index dtype detection + normalization ----------------
// If the index tensor is int64, the high 32-bit word of every entry is 0
// (values are in [0, 1024)). If it is int32, the "high words" are random
// indices in [0,1024): the chance that 1024 of them are all zero is ~0.
__global__ void detect_kernel(const unsigned int* __restrict__ w) {
    unsigned int any = 0;
    for (int i = threadIdx.x; i < 1024; i += 32)
        any |= w[2 * i + 1];
    #pragma unroll
    for (int o = 16; o; o >>= 1)
        any |= __shfl_xor_sync(0xFFFFFFFFu, any, o);
    if (threadIdx.x == 0) g_is64 = (any == 0u) ? 1 : 0;
}

__global__ void convert_kernel(const void* __restrict__ idx) {
    int i = blockIdx.x * blockDim.x + threadIdx.x;   // 0 .. 32767
    if (i >= L_ * KK_) return;
    if (g_is64) g_index[i] = (int)((const long long*)idx)[i];
    else        g_index[i] = ((const int*)idx)[i];
}

// ---------------- q projection: q = user @ Wq^T + bq ----------------
// One warp per output element (8192 outputs), coalesced float4 reads.
__global__ __launch_bounds__(256) void qproj_kernel(
    const float* __restrict__ user, const float* __restrict__ Wq,
    const float* __restrict__ bq)
{
    int o    = (blockIdx.x * blockDim.x + threadIdx.x) >> 5;  // 0..8191
    int lane = threadIdx.x & 31;
    int b = o >> 9;
    int n = o & 511;
    const float4* u4 = reinterpret_cast<const float4*>(user + (size_t)b * H_);
    const float4* w4 = reinterpret_cast<const float4*>(Wq + (size_t)n * H_);
    float acc = 0.f;
    #pragma unroll
    for (int i = lane; i < H_ / 4; i += 32) {
        float4 a = u4[i], w = w4[i];
        acc += a.x * w.x + a.y * w.y + a.z * w.z + a.w * w.w;
    }
    #pragma unroll
    for (int off = 16; off; off >>= 1)
        acc += __shfl_xor_sync(0xFFFFFFFFu, acc, off);
    if (lane == 0) g_q[o] = acc + bq[n];
}

// ---------------- tiled SGEMM: C[m,n] = sum_k A[m,k]*W[n,k] + bias[n] (+ addend[m,n]) ----------------
// 128x128 tile, BK=16, 256 threads, 8x8 per-thread microtile.
__global__ __launch_bounds__(256, 2) void gemm_kernel(
    const float* __restrict__ A, const float* __restrict__ W,
    const float* __restrict__ bias, const float* __restrict__ addend,
    float* __restrict__ C, int M, int N, int Kd)
{
    __shared__ float As[16][132];
    __shared__ float Bs[16][132];

    const int tid = threadIdx.x;
    const int bm  = blockIdx.y * 128;
    const int bn  = blockIdx.x * 128;
    const int tx  = tid & 15;
    const int ty  = tid >> 4;
    const int r0  = tid >> 2;   // 0..63
    const int c0  = tid & 3;    // 0..3

    float acc[8][8];
    #pragma unroll
    for (int i = 0; i < 8; i++)
        #pragma unroll
        for (int j = 0; j < 8; j++) acc[i][j] = 0.f;

    const float* Aptr = A + (size_t)bm * Kd;
    const float* Wptr = W + (size_t)bn * Kd;

    for (int k0 = 0; k0 < Kd; k0 += 16) {
        #pragma unroll
        for (int h = 0; h < 2; h++) {
            int r = r0 + h * 64;
            float4 va = *reinterpret_cast<const float4*>(Aptr + (size_t)r * Kd + k0 + c0 * 4);
            As[c0 * 4 + 0][r] = va.x;
            As[c0 * 4 + 1][r] = va.y;
            As[c0 * 4 + 2][r] = va.z;
            As[c0 * 4 + 3][r] = va.w;
            float4 vb = *reinterpret_cast<const float4*>(Wptr + (size_t)r * Kd + k0 + c0 * 4);
            Bs[c0 * 4 + 0][r] = vb.x;
            Bs[c0 * 4 + 1][r] = vb.y;
            Bs[c0 * 4 + 2][r] = vb.z;
            Bs[c0 * 4 + 3][r] = vb.w;
        }
        __syncthreads();
        #pragma unroll
        for (int kk = 0; kk < 16; kk++) {
            float ra[8], rb[8];
            float4 a0 = *reinterpret_cast<const float4*>(&As[kk][ty * 8]);
            float4 a1 = *reinterpret_cast<const float4*>(&As[kk][ty * 8 + 4]);
            float4 b0 = *reinterpret_cast<const float4*>(&Bs[kk][tx * 8]);
            float4 b1 = *reinterpret_cast<const float4*>(&Bs[kk][tx * 8 + 4]);
            ra[0] = a0.x; ra[1] = a0.y; ra[2] = a0.z; ra[3] = a0.w;
            ra[4] = a1.x; ra[5] = a1.y; ra[6] = a1.z; ra[7] = a1.w;
            rb[0] = b0.x; rb[1] = b0.y; rb[2] = b0.z; rb[3] = b0.w;
            rb[4] = b1.x; rb[5] = b1.y; rb[6] = b1.z; rb[7] = b1.w;
            #pragma unroll
            for (int i = 0; i < 8; i++)
                #pragma unroll
                for (int j = 0; j < 8; j++)
                    acc[i][j] += ra[i] * rb[j];
        }
        __syncthreads();
    }

    #pragma unroll
    for (int i = 0; i < 8; i++) {
        int m = bm + ty * 8 + i;
        float* crow = C + (size_t)m * N + bn + tx * 8;
        #pragma unroll
        for (int j = 0; j < 8; j += 4) {
            float4 bsv = *reinterpret_cast<const float4*>(bias + bn + tx * 8 + j);
            float4 o;
            o.x = acc[i][j + 0] + bsv.x;
            o.y = acc[i][j + 1] + bsv.y;
            o.z = acc[i][j + 2] + bsv.z;
            o.w = acc[i][j + 3] + bsv.w;
            if (addend) {
                float4 ad = *reinterpret_cast<const float4*>(
                    addend + (size_t)m * N + bn + tx * 8 + j);
                o.x += ad.x; o.y += ad.y; o.z += ad.z; o.w += ad.w;
            }
            *reinterpret_cast<float4*>(crow + j) = o;
        }
    }
}

// ---------------- scores: s[b,l] = dot(q[b], k[b,l]) / sqrt(H) ----------------
__global__ __launch_bounds__(256) void score_kernel() {
    int w    = (blockIdx.x * blockDim.x + threadIdx.x) >> 5;  // 0..16383
    int lane = threadIdx.x & 31;
    int b = w >> 10;
    const float4* kr = reinterpret_cast<const float4*>(g_k + (size_t)w * H_);
    const float4* qr = reinterpret_cast<const float4*>(g_q + (size_t)b * H_);
    float acc = 0.f;
    #pragma unroll
    for (int i = lane; i < H_ / 4; i += 32) {
        float4 a = kr[i], q = qr[i];
        acc += a.x * q.x + a.y * q.y + a.z * q.z + a.w * q.w;
    }
    #pragma unroll
    for (int off = 16; off; off >>= 1)
        acc += __shfl_xor_sync(0xFFFFFFFFu, acc, off);
    if (lane == 0) g_s[w] = acc * 0.04419417382415922f;  // 1/sqrt(512)
}

// ---------------- gather + softmax + weighted V sum ----------------
__global__ __launch_bounds__(128) void attn_kernel(const float* __restrict__ mask) {
    __shared__ float wsh[KK_];
    __shared__ int   ish[KK_];
    const int bl  = blockIdx.x;          // 0..16383
    const int b   = bl >> 10;
    const int l   = bl & 1023;
    const int tid = threadIdx.x;

    if (tid < KK_) {
        int   idx = g_index[l * KK_ + tid];
        float s   = g_s[b * L_ + idx] + mask[(size_t)bl * KK_ + tid];
        ish[tid]  = idx;
        float mx = s;
        #pragma unroll
        for (int o = 16; o; o >>= 1)
            mx = fmaxf(mx, __shfl_xor_sync(0xFFFFFFFFu, mx, o));
        float e = expf(s - mx);
        float sum = e;
        #pragma unroll
        for (int o = 16; o; o >>= 1)
            sum += __shfl_xor_sync(0xFFFFFFFFu, sum, o);
        wsh[tid] = e / sum;
    }
    __syncthreads();

    const float4* v4 = reinterpret_cast<const float4*>(g_v);
    float4 acc = make_float4(0.f, 0.f, 0.f, 0.f);
    #pragma unroll 8
    for (int k = 0; k < KK_; k++) {
        float  wk = wsh[k];
        float4 vv = v4[((size_t)(b * L_ + ish[k])) * (H_ / 4) + tid];
        acc.x += wk * vv.x;
        acc.y += wk * vv.y;
        acc.z += wk * vv.z;
        acc.w += wk * vv.w;
    }
    reinterpret_cast<float4*>(g_attn)[(size_t)bl * (H_ / 4) + tid] = acc;
}

// ---------------- layernorm over H, write final output ----------------
__global__ __launch_bounds__(128) void ln_kernel(
    const float* __restrict__ gma, const float* __restrict__ bta,
    float* __restrict__ out)
{
    const int row = blockIdx.x;
    const int tid = threadIdx.x;
    const float4 v = reinterpret_cast<const float4*>(g_x)[(size_t)row * (H_ / 4) + tid];

    float s  = v.x + v.y + v.z + v.w;
    float ss = v.x * v.x + v.y * v.y + v.z * v.z + v.w * v.w;
    #pragma unroll
    for (int o = 16; o; o >>= 1) {
        s  += __shfl_xor_sync(0xFFFFFFFFu, s, o);
        ss += __shfl_xor_sync(0xFFFFFFFFu, ss, o);
    }
    __shared__ float sh[8];
    int wid = tid >> 5, lane = tid & 31;
    if (lane == 0) { sh[wid] = s; sh[4 + wid] = ss; }
    __syncthreads();
    if (tid == 0) {
        float S  = sh[0] + sh[1] + sh[2] + sh[3];
        float SS = sh[4] + sh[5] + sh[6] + sh[7];
        sh[0] = S; sh[1] = SS;
    }
    __syncthreads();
    float mu  = sh[0] * (1.f / 512.f);
    float var = sh[1] * (1.f / 512.f) - mu * mu;
    float inv = rsqrtf(var + 1e-12f);

    float4 g4 = reinterpret_cast<const float4*>(gma)[tid];
    float4 b4 = reinterpret_cast<const float4*>(bta)[tid];
    float4 o;
    o.x = (v.x - mu) * inv * g4.x + b4.x;
    o.y = (v.y - mu) * inv * g4.y + b4.y;
    o.z = (v.z - mu) * inv * g4.z + b4.z;
    o.w = (v.w - mu) * inv * g4.w + b4.w;
    reinterpret_cast<float4*>(out)[(size_t)row * (H_ / 4) + tid] = o;
}

// ---------------- launch ----------------
extern "C" void kernel_launch(void* const* d_in, const int* in_sizes, int n_in,
                              void* d_out, int out_size)
{
    const float* user  = (const float*)d_in[0];
    const float* item  = (const float*)d_in[1];
    const float* mask  = (const float*)d_in[2];
    const void*  indexp =               d_in[3];
    const float* Wq    = (const float*)d_in[4];
    const float* bq    = (const float*)d_in[5];
    const float* Wk    = (const float*)d_in[6];
    const float* bk    = (const float*)d_in[7];
    const float* Wv    = (const float*)d_in[8];
    const float* bv    = (const float*)d_in[9];
    const float* Wd    = (const float*)d_in[10];
    const float* bd    = (const float*)d_in[11];
    const float* lng   = (const float*)d_in[12];
    const float* lnb   = (const float*)d_in[13];
    float* out = (float*)d_out;

    float *kp, *vp, *attnp, *xp;
    cudaGetSymbolAddress((void**)&kp,    g_k);
    cudaGetSymbolAddress((void**)&vp,    g_v);
    cudaGetSymbolAddress((void**)&attnp, g_attn);
    cudaGetSymbolAddress((void**)&xp,    g_x);

    // index normalization (int32 vs int64 detection)
    detect_kernel<<<1, 32>>>((const unsigned int*)indexp);
    convert_kernel<<<(L_ * KK_ + 255) / 256, 256>>>(indexp);

    // q projection (tiny)
    qproj_kernel<<<(B_ * H_) / 8, 256>>>(user, Wq, bq);

    // k = item @ Wk^T + bk ;  v = item @ Wv^T + bv
    dim3 ggrid(H_ / 128, BL_ / 128);   // (4, 128)
    gemm_kernel<<<ggrid, 256>>>(item, Wk, bk, nullptr, kp, BL_, H_, H_);
    gemm_kernel<<<ggrid, 256>>>(item, Wv, bv, nullptr, vp, BL_, H_, H_);

    // scores
    score_kernel<<<BL_ / 8, 256>>>();

    // gather + softmax + weighted sum
    attn_kernel<<<BL_, 128>>>(mask);

    // dense = attn @ Wd^T + bd + item  (residual fused into epilogue)
    gemm_kernel<<<ggrid, 256>>>(attnp, Wd, bd, item, xp, BL_, H_, H_);

    // layernorm -> out
    ln_kernel<<<BL_, 128>>>(lng, lnb, out);
}

// round 4
// speedup vs baseline: 2.1585x; 2.1585x over previous
#include <cuda_runtime.h>
#include <math.h>
#include <stdint.h>

#define B_  16
#define L_  1024
#define H_  512
#define KK_ 32
#define BL_ (B_ * L_)          // 16384

// ---------------- scratch (no allocations allowed) ----------------
__device__ float g_q[B_ * H_];
__device__ float g_k[BL_ * H_];
__device__ float g_v[BL_ * H_];
__device__ float g_s[B_ * L_];
__device__ float g_attn[BL_ * H_];
__device__ float g_x[BL_ * H_];
__device__ float g_itemc[BL_ * H_];   // tf32-rounded item
__device__ float g_wkc[H_ * H_];      // tf32-rounded weights
__device__ float g_wvc[H_ * H_];
__device__ float g_wdc[H_ * H_];
__device__ int   g_index[L_ * KK_];
__device__ int   g_is64;

__device__ __forceinline__ float tf32r(float x) {
    uint32_t u;
    asm("cvt.rna.tf32.f32 %0, %1;" : "=r"(u) : "f"(x));
    return __uint_as_float(u);
}
__device__ __forceinline__ void cp16(uint32_t d, const void* g) {
    asm volatile("cp.async.cg.shared.global [%0], [%1], 16;" :: "r"(d), "l"(g));
}
__device__ __forceinline__ uint32_t smem_u32(const void* p) {
    uint32_t a;
    asm("{ .reg .u64 t; cvta.to.shared.u64 t, %1; cvt.u32.u64 %0, t; }" : "=r"(a) : "l"(p));
    return a;
}

// ---------------- index dtype detection + normalization ----------------
__global__ void detect_kernel(const unsigned int* __restrict__ w) {
    unsigned int any = 0;
    for (int i = threadIdx.x; i < 1024; i += 32)
        any |= w[2 * i + 1];
    #pragma unroll
    for (int o = 16; o; o >>= 1)
        any |= __shfl_xor_sync(0xFFFFFFFFu, any, o);
    if (threadIdx.x == 0) g_is64 = (any == 0u) ? 1 : 0;
}

__global__ void convert_kernel(const void* __restrict__ idx) {
    int i = blockIdx.x * blockDim.x + threadIdx.x;
    if (i >= L_ * KK_) return;
    if (g_is64) g_index[i] = (int)((const long long*)idx)[i];
    else        g_index[i] = ((const int*)idx)[i];
}

// ---------------- tf32 round-to-nearest pre-pass ----------------
__global__ __launch_bounds__(256) void tf32_round_kernel(
    const float* __restrict__ in, float* __restrict__ out, int n4)
{
    int i = blockIdx.x * blockDim.x + threadIdx.x;
    if (i >= n4) return;
    float4 v = reinterpret_cast<const float4*>(in)[i];
    v.x = tf32r(v.x); v.y = tf32r(v.y); v.z = tf32r(v.z); v.w = tf32r(v.w);
    reinterpret_cast<float4*>(out)[i] = v;
}

// ---------------- q projection (tiny, fp32) ----------------
__global__ __launch_bounds__(256) void qproj_kernel(
    const float* __restrict__ user, const float* __restrict__ Wq,
    const float* __restrict__ bq)
{
    int o    = (blockIdx.x * blockDim.x + threadIdx.x) >> 5;
    int lane = threadIdx.x & 31;
    int b = o >> 9;
    int n = o & 511;
    const float4* u4 = reinterpret_cast<const float4*>(user + (size_t)b * H_);
    const float4* w4 = reinterpret_cast<const float4*>(Wq + (size_t)n * H_);
    float acc = 0.f;
    #pragma unroll
    for (int i = lane; i < H_ / 4; i += 32) {
        float4 a = u4[i], w = w4[i];
        acc += a.x * w.x + a.y * w.y + a.z * w.z + a.w * w.w;
    }
    #pragma unroll
    for (int off = 16; off; off >>= 1)
        acc += __shfl_xor_sync(0xFFFFFFFFu, acc, off);
    if (lane == 0) g_q[o] = acc + bq[n];
}

// ================= tf32 mma.sync GEMM =================
// C[m,n] = sum_k A[m,k] * W[n,k] + bias[n] (+ addend[m,n])
// CTA tile 128x128, BK=32, 8 warps (2m x 4n), warp tile 64x32,
// double-buffered cp.async, smem row stride 36 floats.
#define GS_STRIDE 36
#define GS_TILE   (128 * GS_STRIDE)               // floats per (A or B) stage
#define GS_SMEM   (4 * GS_TILE * 4)               // bytes: 2 stages x (A+B)

__device__ __forceinline__ void mma_tf32(float* d, const uint32_t* a, const uint32_t* b) {
    asm volatile(
        "mma.sync.aligned.m16n8k8.row.col.f32.tf32.tf32.f32 "
        "{%0,%1,%2,%3}, {%4,%5,%6,%7}, {%8,%9}, {%0,%1,%2,%3};"
        : "+f"(d[0]), "+f"(d[1]), "+f"(d[2]), "+f"(d[3])
        : "r"(a[0]), "r"(a[1]), "r"(a[2]), "r"(a[3]), "r"(b[0]), "r"(b[1]));
}

__global__ __launch_bounds__(256) void gemm_tc_kernel(
    const float* __restrict__ A, const float* __restrict__ W,
    const float* __restrict__ bias, const float* __restrict__ addend,
    float* __restrict__ C)
{
    extern __shared__ float sm[];
    float* As[2] = { sm,               sm + GS_TILE };
    float* Bs[2] = { sm + 2 * GS_TILE, sm + 3 * GS_TILE };

    const int tid  = threadIdx.x;
    const int lane = tid & 31;
    const int warp = tid >> 5;
    const int wm   = (warp & 1) * 64;      // warp m offset
    const int wn   = (warp >> 1) * 32;     // warp n offset
    const int g    = lane >> 2;            // 0..7
    const int t    = lane & 3;             // 0..3
    const int bm   = blockIdx.y * 128;
    const int bn   = blockIdx.x * 128;

    // per-thread load coords (4 rows apart per i): e = i*256 + tid
    const int lrow = tid >> 3;             // 0..31 (+32 per i)
    const int lc   = tid & 7;              // k-group of 4

    const float* Abase = A + (size_t)bm * H_ + lc * 4;
    const float* Bbase = W + (size_t)bn * H_ + lc * 4;

    float acc[4][4][4];
    #pragma unroll
    for (int mi = 0; mi < 4; mi++)
        #pragma unroll
        for (int ni = 0; ni < 4; ni++)
            #pragma unroll
            for (int r = 0; r < 4; r++) acc[mi][ni][r] = 0.f;

    // ---- issue stage 0 ----
    {
        uint32_t a0 = smem_u32(As[0]), b0 = smem_u32(Bs[0]);
        #pragma unroll
        for (int i = 0; i < 4; i++) {
            int row = lrow + i * 32;
            uint32_t off = (uint32_t)(row * GS_STRIDE + lc * 4) * 4;
            cp16(a0 + off, Abase + (size_t)row * H_);
            cp16(b0 + off, Bbase + (size_t)row * H_);
        }
        asm volatile("cp.async.commit_group;" ::: "memory");
    }

    const int NST = H_ / 32;   // 16
    for (int s = 0; s < NST; s++) {
        const int buf = s & 1;
        if (s + 1 < NST) {
            const int k0 = (s + 1) * 32;
            uint32_t a1 = smem_u32(As[buf ^ 1]), b1 = smem_u32(Bs[buf ^ 1]);
            #pragma unroll
            for (int i = 0; i < 4; i++) {
                int row = lrow + i * 32;
                uint32_t off = (uint32_t)(row * GS_STRIDE + lc * 4) * 4;
                cp16(a1 + off, Abase + (size_t)row * H_ + k0);
                cp16(b1 + off, Bbase + (size_t)row * H_ + k0);
            }
            asm volatile("cp.async.commit_group;" ::: "memory");
            asm volatile("cp.async.wait_group 1;" ::: "memory");
        } else {
            asm volatile("cp.async.wait_group 0;" ::: "memory");
        }
        __syncthreads();

        const uint32_t* Au = reinterpret_cast<const uint32_t*>(As[buf]);
        const uint32_t* Bu = reinterpret_cast<const uint32_t*>(Bs[buf]);
        #pragma unroll
        for (int kk = 0; kk < 4; kk++) {
            const int k = kk * 8;
            uint32_t af[4][4], bf[4][2];
            #pragma unroll
            for (int mi = 0; mi < 4; mi++) {
                int row = wm + mi * 16 + g;
                af[mi][0] = Au[row * GS_STRIDE + k + t];
                af[mi][1] = Au[(row + 8) * GS_STRIDE + k + t];
                af[mi][2] = Au[row * GS_STRIDE + k + t + 4];
                af[mi][3] = Au[(row + 8) * GS_STRIDE + k + t + 4];
            }
            #pragma unroll
            for (int ni = 0; ni < 4; ni++) {
                int col = wn + ni * 8 + g;
                bf[ni][0] = Bu[col * GS_STRIDE + k + t];
                bf[ni][1] = Bu[col * GS_STRIDE + k + t + 4];
            }
            #pragma unroll
            for (int mi = 0; mi < 4; mi++)
                #pragma unroll
                for (int ni = 0; ni < 4; ni++)
                    mma_tf32(acc[mi][ni], af[mi], bf[ni]);
        }
        __syncthreads();
    }

    // ---- epilogue: bias (+addend), float2 stores ----
    #pragma unroll
    for (int mi = 0; mi < 4; mi++) {
        const int m0 = bm + wm + mi * 16 + g;
        #pragma unroll
        for (int ni = 0; ni < 4; ni++) {
            const int n = bn + wn + ni * 8 + 2 * t;
            float2 bs = *reinterpret_cast<const float2*>(bias + n);
            float2 o0, o1;
            o0.x = acc[mi][ni][0] + bs.x;
            o0.y = acc[mi][ni][1] + bs.y;
            o1.x = acc[mi][ni][2] + bs.x;
            o1.y = acc[mi][ni][3] + bs.y;
            if (addend) {
                float2 a0 = *reinterpret_cast<const float2*>(addend + (size_t)m0 * H_ + n);
                float2 a1 = *reinterpret_cast<const float2*>(addend + (size_t)(m0 + 8) * H_ + n);
                o0.x += a0.x; o0.y += a0.y;
                o1.x += a1.x; o1.y += a1.y;
            }
            *reinterpret_cast<float2*>(C + (size_t)m0 * H_ + n)       = o0;
            *reinterpret_cast<float2*>(C + (size_t)(m0 + 8) * H_ + n) = o1;
        }
    }
}

// ---------------- scores: s[b,l] = dot(q[b], k[b,l]) / sqrt(H) ----------------
__global__ __launch_bounds__(256) void score_kernel() {
    int w    = (blockIdx.x * blockDim.x + threadIdx.x) >> 5;
    int lane = threadIdx.x & 31;
    int b = w >> 10;
    const float4* kr = reinterpret_cast<const float4*>(g_k + (size_t)w * H_);
    const float4* qr = reinterpret_cast<const float4*>(g_q + (size_t)b * H_);
    float acc = 0.f;
    #pragma unroll
    for (int i = lane; i < H_ / 4; i += 32) {
        float4 a = kr[i], q = qr[i];
        acc += a.x * q.x + a.y * q.y + a.z * q.z + a.w * q.w;
    }
    #pragma unroll
    for (int off = 16; off; off >>= 1)
        acc += __shfl_xor_sync(0xFFFFFFFFu, acc, off);
    if (lane == 0) g_s[w] = acc * 0.04419417382415922f;
}

// ---------------- gather + softmax + weighted V sum (tf32-rounded out) ----------------
__global__ __launch_bounds__(128) void attn_kernel(const float* __restrict__ mask) {
    __shared__ float wsh[KK_];
    __shared__ int   ish[KK_];
    const int bl  = blockIdx.x;
    const int b   = bl >> 10;
    const int l   = bl & 1023;
    const int tid = threadIdx.x;

    if (tid < KK_) {
        int   idx = g_index[l * KK_ + tid];
        float s   = g_s[b * L_ + idx] + mask[(size_t)bl * KK_ + tid];
        ish[tid]  = idx;
        float mx = s;
        #pragma unroll
        for (int o = 16; o; o >>= 1)
            mx = fmaxf(mx, __shfl_xor_sync(0xFFFFFFFFu, mx, o));
        float e = expf(s - mx);
        float sum = e;
        #pragma unroll
        for (int o = 16; o; o >>= 1)
            sum += __shfl_xor_sync(0xFFFFFFFFu, sum, o);
        wsh[tid] = e / sum;
    }
    __syncthreads();

    const float4* v4 = reinterpret_cast<const float4*>(g_v);
    float4 acc = make_float4(0.f, 0.f, 0.f, 0.f);
    #pragma unroll 8
    for (int k = 0; k < KK_; k++) {
        float  wk = wsh[k];
        float4 vv = v4[((size_t)(b * L_ + ish[k])) * (H_ / 4) + tid];
        acc.x += wk * vv.x;
        acc.y += wk * vv.y;
        acc.z += wk * vv.z;
        acc.w += wk * vv.w;
    }
    acc.x = tf32r(acc.x); acc.y = tf32r(acc.y);
    acc.z = tf32r(acc.z); acc.w = tf32r(acc.w);
    reinterpret_cast<float4*>(g_attn)[(size_t)bl * (H_ / 4) + tid] = acc;
}

// ---------------- layernorm ----------------
__global__ __launch_bounds__(128) void ln_kernel(
    const float* __restrict__ gma, const float* __restrict__ bta,
    float* __restrict__ out)
{
    const int row = blockIdx.x;
    const int tid = threadIdx.x;
    const float4 v = reinterpret_cast<const float4*>(g_x)[(size_t)row * (H_ / 4) + tid];

    float s  = v.x + v.y + v.z + v.w;
    float ss = v.x * v.x + v.y * v.y + v.z * v.z + v.w * v.w;
    #pragma unroll
    for (int o = 16; o; o >>= 1) {
        s  += __shfl_xor_sync(0xFFFFFFFFu, s, o);
        ss += __shfl_xor_sync(0xFFFFFFFFu, ss, o);
    }
    __shared__ float sh[8];
    int wid = tid >> 5, lane = tid & 31;
    if (lane == 0) { sh[wid] = s; sh[4 + wid] = ss; }
    __syncthreads();
    if (tid == 0) {
        float S  = sh[0] + sh[1] + sh[2] + sh[3];
        float SS = sh[4] + sh[5] + sh[6] + sh[7];
        sh[0] = S; sh[1] = SS;
    }
    __syncthreads();
    float mu  = sh[0] * (1.f / 512.f);
    float var = sh[1] * (1.f / 512.f) - mu * mu;
    float inv = rsqrtf(var + 1e-12f);

    float4 g4 = reinterpret_cast<const float4*>(gma)[tid];
    float4 b4 = reinterpret_cast<const float4*>(bta)[tid];
    float4 o;
    o.x = (v.x - mu) * inv * g4.x + b4.x;
    o.y = (v.y - mu) * inv * g4.y + b4.y;
    o.z = (v.z - mu) * inv * g4.z + b4.z;
    o.w = (v.w - mu) * inv * g4.w + b4.w;
    reinterpret_cast<float4*>(out)[(size_t)row * (H_ / 4) + tid] = o;
}

// ---------------- launch ----------------
extern "C" void kernel_launch(void* const* d_in, const int* in_sizes, int n_in,
                              void* d_out, int out_size)
{
    const float* user  = (const float*)d_in[0];
    const float* item  = (const float*)d_in[1];
    const float* mask  = (const float*)d_in[2];
    const void*  indexp =               d_in[3];
    const float* Wq    = (const float*)d_in[4];
    const float* bq    = (const float*)d_in[5];
    const float* Wk    = (const float*)d_in[6];
    const float* bk    = (const float*)d_in[7];
    const float* Wv    = (const float*)d_in[8];
    const float* bv    = (const float*)d_in[9];
    const float* Wd    = (const float*)d_in[10];
    const float* bd    = (const float*)d_in[11];
    const float* lng   = (const float*)d_in[12];
    const float* lnb   = (const float*)d_in[13];
    float* out = (float*)d_out;

    float *kp, *vp, *attnp, *xp, *itemc, *wkc, *wvc, *wdc;
    cudaGetSymbolAddress((void**)&kp,    g_k);
    cudaGetSymbolAddress((void**)&vp,    g_v);
    cudaGetSymbolAddress((void**)&attnp, g_attn);
    cudaGetSymbolAddress((void**)&xp,    g_x);
    cudaGetSymbolAddress((void**)&itemc, g_itemc);
    cudaGetSymbolAddress((void**)&wkc,   g_wkc);
    cudaGetSymbolAddress((void**)&wvc,   g_wvc);
    cudaGetSymbolAddress((void**)&wdc,   g_wdc);

    cudaFuncSetAttribute(gemm_tc_kernel, cudaFuncAttributeMaxDynamicSharedMemorySize, GS_SMEM);

    // index normalization
    detect_kernel<<<1, 32>>>((const unsigned int*)indexp);
    convert_kernel<<<(L_ * KK_ + 255) / 256, 256>>>(indexp);

    // tf32 RN pre-rounding of GEMM inputs
    tf32_round_kernel<<<(BL_ * H_ / 4 + 255) / 256, 256>>>(item, itemc, BL_ * H_ / 4);
    tf32_round_kernel<<<(H_ * H_ / 4 + 255) / 256, 256>>>(Wk, wkc, H_ * H_ / 4);
    tf32_round_kernel<<<(H_ * H_ / 4 + 255) / 256, 256>>>(Wv, wvc, H_ * H_ / 4);
    tf32_round_kernel<<<(H_ * H_ / 4 + 255) / 256, 256>>>(Wd, wdc, H_ * H_ / 4);

    // q projection (tiny, full fp32)
    qproj_kernel<<<(B_ * H_) / 8, 256>>>(user, Wq, bq);

    // k / v projections on tensor cores
    dim3 ggrid(H_ / 128, BL_ / 128);   // (4, 128)
    gemm_tc_kernel<<<ggrid, 256, GS_SMEM>>>(itemc, wkc, bk, nullptr, kp);
    gemm_tc_kernel<<<ggrid, 256, GS_SMEM>>>(itemc, wvc, bv, nullptr, vp);

    // scores
    score_kernel<<<BL_ / 8, 256>>>();

    // gather + softmax + weighted sum (writes tf32-rounded attn)
    attn_kernel<<<BL_, 128>>>(mask);

    // dense = attn @ Wd^T + bd + item (residual fused)
    gemm_tc_kernel<<<ggrid, 256, GS_SMEM>>>(attnp, wdc, bd, item, xp);

    // layernorm -> out
    ln_kernel<<<BL_, 128>>>(lng, lnb, out);
}

// round 5
// speedup vs baseline: 2.6881x; 1.2454x over previous
#include <cuda_runtime.h>
#include <cuda_bf16.h>
#include <math.h>
#include <stdint.h>

#define B_  16
#define L_  1024
#define H_  512
#define KK_ 32
#define BL_ (B_ * L_)          // 16384

// ---------------- scratch (no allocations allowed) ----------------
__device__ float g_q[B_ * H_];
__device__ float g_k[BL_ * H_];
__device__ __nv_bfloat16 g_vh[BL_ * H_];   // V in bf16 (gather traffic halved)
__device__ float g_s[B_ * L_];
__device__ float g_attn[BL_ * H_];
__device__ float g_x[BL_ * H_];
__device__ float g_itemc[BL_ * H_];        // tf32-rounded item
__device__ float g_wfuse[2 * H_ * H_];     // [Wk ; Wv] tf32-rounded
__device__ float g_wdc[H_ * H_];           // Wd tf32-rounded
__device__ float g_bfuse[2 * H_];          // [bk ; bv]
__device__ int   g_index[L_ * KK_];
__device__ int   g_is64;

__device__ __forceinline__ float tf32r(float x) {
    uint32_t u;
    asm("cvt.rna.tf32.f32 %0, %1;" : "=r"(u) : "f"(x));
    return __uint_as_float(u);
}
__device__ __forceinline__ void cp16(uint32_t d, const void* g) {
    asm volatile("cp.async.cg.shared.global [%0], [%1], 16;" :: "r"(d), "l"(g));
}
__device__ __forceinline__ uint32_t smem_u32(const void* p) {
    uint32_t a;
    asm("{ .reg .u64 t; cvta.to.shared.u64 t, %1; cvt.u32.u64 %0, t; }" : "=r"(a) : "l"(p));
    return a;
}
__device__ __forceinline__ void mma_tf32(float* d, const uint32_t* a, const uint32_t* b) {
    asm volatile(
        "mma.sync.aligned.m16n8k8.row.col.f32.tf32.tf32.f32 "
        "{%0,%1,%2,%3}, {%4,%5,%6,%7}, {%8,%9}, {%0,%1,%2,%3};"
        : "+f"(d[0]), "+f"(d[1]), "+f"(d[2]), "+f"(d[3])
        : "r"(a[0]), "r"(a[1]), "r"(a[2]), "r"(a[3]), "r"(b[0]), "r"(b[1]));
}

// ---------------- (1) index dtype detection ----------------
__global__ void detect_kernel(const unsigned int* __restrict__ w) {
    unsigned int any = 0;
    for (int i = threadIdx.x; i < 1024; i += 32)
        any |= w[2 * i + 1];
    #pragma unroll
    for (int o = 16; o; o >>= 1)
        any |= __shfl_xor_sync(0xFFFFFFFFu, any, o);
    if (threadIdx.x == 0) g_is64 = (any == 0u) ? 1 : 0;
}

// ---------------- (2) index normalization ----------------
__global__ void convert_kernel(const void* __restrict__ idx) {
    int i = blockIdx.x * blockDim.x + threadIdx.x;
    if (i >= L_ * KK_) return;
    if (g_is64) g_index[i] = (int)((const long long*)idx)[i];
    else        g_index[i] = ((const int*)idx)[i];
}

// ---------------- (3) tf32 round of item ----------------
__global__ __launch_bounds__(256) void round_item_kernel(
    const float* __restrict__ in, float* __restrict__ out, int n4)
{
    int i = blockIdx.x * blockDim.x + threadIdx.x;
    if (i >= n4) return;
    float4 v = reinterpret_cast<const float4*>(in)[i];
    v.x = tf32r(v.x); v.y = tf32r(v.y); v.z = tf32r(v.z); v.w = tf32r(v.w);
    reinterpret_cast<float4*>(out)[i] = v;
}

// ---------------- (4) round all weights + pack biases (one launch) ----------------
#define WQ4 (H_ * H_ / 4)   // 65536 float4 per weight matrix
__global__ __launch_bounds__(256) void round_w_kernel(
    const float* __restrict__ Wk, const float* __restrict__ Wv,
    const float* __restrict__ Wd, const float* __restrict__ bk,
    const float* __restrict__ bv)
{
    int i = blockIdx.x * blockDim.x + threadIdx.x;
    if (i < 3 * WQ4) {
        const float* src; float* dst; int j = i;
        if (i < WQ4)            { src = Wk; dst = g_wfuse;              }
        else if (i < 2 * WQ4)   { src = Wv; dst = g_wfuse + H_ * H_; j -= WQ4; }
        else                    { src = Wd; dst = g_wdc;   j -= 2 * WQ4; }
        float4 v = reinterpret_cast<const float4*>(src)[j];
        v.x = tf32r(v.x); v.y = tf32r(v.y); v.z = tf32r(v.z); v.w = tf32r(v.w);
        reinterpret_cast<float4*>(dst)[j] = v;
    } else {
        int j = i - 3 * WQ4;            // 0..255 -> 256 float4 of biases
        if (j < 256) {
            float4 v = (j < 128) ? reinterpret_cast<const float4*>(bk)[j]
                                 : reinterpret_cast<const float4*>(bv)[j - 128];
            reinterpret_cast<float4*>(g_bfuse)[j] = v;
        }
    }
}

// ---------------- (5) q projection (tiny, fp32) ----------------
__global__ __launch_bounds__(256) void qproj_kernel(
    const float* __restrict__ user, const float* __restrict__ Wq,
    const float* __restrict__ bq)
{
    int o    = (blockIdx.x * blockDim.x + threadIdx.x) >> 5;
    int lane = threadIdx.x & 31;
    int b = o >> 9;
    int n = o & 511;
    const float4* u4 = reinterpret_cast<const float4*>(user + (size_t)b * H_);
    const float4* w4 = reinterpret_cast<const float4*>(Wq + (size_t)n * H_);
    float acc = 0.f;
    #pragma unroll
    for (int i = lane; i < H_ / 4; i += 32) {
        float4 a = u4[i], w = w4[i];
        acc += a.x * w.x + a.y * w.y + a.z * w.z + a.w * w.w;
    }
    #pragma unroll
    for (int off = 16; off; off >>= 1)
        acc += __shfl_xor_sync(0xFFFFFFFFu, acc, off);
    if (lane == 0) g_q[o] = acc + bq[n];
}

// ================= (6/9) tf32 mma.sync GEMM =================
// CTA tile 128x128, 4 warps (warp tile 64x64), BK=32, 3-stage cp.async ring.
// mode 0: C = A@W^T + bias + addend   (fp32 out)
// mode 1: KV split -> n<512: K fp32 out; n>=512: V bf16 out. bias=g_bfuse.
#define GS_STRIDE 36
#define GS_TILE   (128 * GS_STRIDE)               // 4608 floats per matrix stage
#define GS_SLOT   (2 * GS_TILE)                   // A + B per slot
#define GS_SMEM   (3 * GS_SLOT * 4)               // 110592 bytes

__global__ void __launch_bounds__(128) gemm_tc_kernel(
    const float* __restrict__ A, const float* __restrict__ W,
    const float* __restrict__ bias, const float* __restrict__ addend,
    float* __restrict__ Cf, __nv_bfloat16* __restrict__ Cv, int mode)
{
    extern __shared__ float sm[];

    const int tid  = threadIdx.x;
    const int lane = tid & 31;
    const int warp = tid >> 5;
    const int wm   = (warp & 1) * 64;
    const int wn   = (warp >> 1) * 64;
    const int g    = lane >> 2;
    const int t    = lane & 3;
    const int bm   = blockIdx.y * 128;
    const int bn   = blockIdx.x * 128;

    const int lrow = tid >> 3;             // 0..15 (+16 per i)
    const int lc   = tid & 7;

    const float* Abase = A + (size_t)bm * H_ + lc * 4;
    const float* Bbase = W + (size_t)bn * H_ + lc * 4;

    float acc[4][8][4];
    #pragma unroll
    for (int mi = 0; mi < 4; mi++)
        #pragma unroll
        for (int ni = 0; ni < 8; ni++)
            #pragma unroll
            for (int r = 0; r < 4; r++) acc[mi][ni][r] = 0.f;

    const uint32_t smb = smem_u32(sm);
    const int NST = H_ / 32;   // 16

    // prologue: stages 0,1 -> slots 0,1
    #pragma unroll
    for (int p = 0; p < 2; p++) {
        const uint32_t ab = smb + (uint32_t)(p * GS_SLOT) * 4;
        const uint32_t bb = ab + GS_TILE * 4;
        const int k0 = p * 32;
        #pragma unroll
        for (int i = 0; i < 8; i++) {
            int row = lrow + i * 16;
            uint32_t off = (uint32_t)(row * GS_STRIDE + lc * 4) * 4;
            cp16(ab + off, Abase + (size_t)row * H_ + k0);
            cp16(bb + off, Bbase + (size_t)row * H_ + k0);
        }
        asm volatile("cp.async.commit_group;" ::: "memory");
    }

    for (int s = 0; s < NST; s++) {
        if (s < NST - 1) asm volatile("cp.async.wait_group 1;" ::: "memory");
        else             asm volatile("cp.async.wait_group 0;" ::: "memory");
        __syncthreads();

        if (s + 2 < NST) {   // issue stage s+2 into slot freed by stage s-1
            const int slot = (s + 2) % 3;
            const uint32_t ab = smb + (uint32_t)(slot * GS_SLOT) * 4;
            const uint32_t bb = ab + GS_TILE * 4;
            const int k0 = (s + 2) * 32;
            #pragma unroll
            for (int i = 0; i < 8; i++) {
                int row = lrow + i * 16;
                uint32_t off = (uint32_t)(row * GS_STRIDE + lc * 4) * 4;
                cp16(ab + off, Abase + (size_t)row * H_ + k0);
                cp16(bb + off, Bbase + (size_t)row * H_ + k0);
            }
            asm volatile("cp.async.commit_group;" ::: "memory");
        }

        const float* slotp = sm + (s % 3) * GS_SLOT;
        const uint32_t* Au = reinterpret_cast<const uint32_t*>(slotp);
        const uint32_t* Bu = reinterpret_cast<const uint32_t*>(slotp + GS_TILE);
        #pragma unroll
        for (int kk = 0; kk < 4; kk++) {
            const int k = kk * 8;
            uint32_t af[4][4], bf[8][2];
            #pragma unroll
            for (int mi = 0; mi < 4; mi++) {
                int row = wm + mi * 16 + g;
                af[mi][0] = Au[row * GS_STRIDE + k + t];
                af[mi][1] = Au[(row + 8) * GS_STRIDE + k + t];
                af[mi][2] = Au[row * GS_STRIDE + k + t + 4];
                af[mi][3] = Au[(row + 8) * GS_STRIDE + k + t + 4];
            }
            #pragma unroll
            for (int ni = 0; ni < 8; ni++) {
                int col = wn + ni * 8 + g;
                bf[ni][0] = Bu[col * GS_STRIDE + k + t];
                bf[ni][1] = Bu[col * GS_STRIDE + k + t + 4];
            }
            #pragma unroll
            for (int mi = 0; mi < 4; mi++)
                #pragma unroll
                for (int ni = 0; ni < 8; ni++)
                    mma_tf32(acc[mi][ni], af[mi], bf[ni]);
        }
    }

    // ---- epilogue ----
    const bool vside = (mode == 1) && (bn >= 512);
    #pragma unroll
    for (int mi = 0; mi < 4; mi++) {
        const int m0 = bm + wm + mi * 16 + g;
        #pragma unroll
        for (int ni = 0; ni < 8; ni++) {
            const int n = bn + wn + ni * 8 + 2 * t;
            float2 bs = *reinterpret_cast<const float2*>(bias + n);
            float2 o0, o1;
            o0.x = acc[mi][ni][0] + bs.x;
            o0.y = acc[mi][ni][1] + bs.y;
            o1.x = acc[mi][ni][2] + bs.x;
            o1.y = acc[mi][ni][3] + bs.y;
            if (mode == 0) {
                float2 a0 = *reinterpret_cast<const float2*>(addend + (size_t)m0 * H_ + n);
                float2 a1 = *reinterpret_cast<const float2*>(addend + (size_t)(m0 + 8) * H_ + n);
                o0.x += a0.x; o0.y += a0.y;
                o1.x += a1.x; o1.y += a1.y;
            }
            if (vside) {
                const int c = n - 512;
                *reinterpret_cast<__nv_bfloat162*>(Cv + (size_t)m0 * H_ + c) =
                    __floats2bfloat162_rn(o0.x, o0.y);
                *reinterpret_cast<__nv_bfloat162*>(Cv + (size_t)(m0 + 8) * H_ + c) =
                    __floats2bfloat162_rn(o1.x, o1.y);
            } else {
                *reinterpret_cast<float2*>(Cf + (size_t)m0 * H_ + n)       = o0;
                *reinterpret_cast<float2*>(Cf + (size_t)(m0 + 8) * H_ + n) = o1;
            }
        }
    }
}

// ---------------- (7) scores ----------------
__global__ __launch_bounds__(256) void score_kernel() {
    int w    = (blockIdx.x * blockDim.x + threadIdx.x) >> 5;
    int lane = threadIdx.x & 31;
    int b = w >> 10;
    const float4* kr = reinterpret_cast<const float4*>(g_k + (size_t)w * H_);
    const float4* qr = reinterpret_cast<const float4*>(g_q + (size_t)b * H_);
    float acc = 0.f;
    #pragma unroll
    for (int i = lane; i < H_ / 4; i += 32) {
        float4 a = kr[i], q = qr[i];
        acc += a.x * q.x + a.y * q.y + a.z * q.z + a.w * q.w;
    }
    #pragma unroll
    for (int off = 16; off; off >>= 1)
        acc += __shfl_xor_sync(0xFFFFFFFFu, acc, off);
    if (lane == 0) g_s[w] = acc * 0.04419417382415922f;
}

// ---------------- (8) gather + softmax + weighted bf16-V sum ----------------
__global__ __launch_bounds__(128) void attn_kernel(const float* __restrict__ mask) {
    __shared__ float wsh[KK_];
    __shared__ int   ish[KK_];
    const int bl  = blockIdx.x;
    const int b   = bl >> 10;
    const int l   = bl & 1023;
    const int tid = threadIdx.x;

    if (tid < KK_) {
        int   idx = g_index[l * KK_ + tid];
        float s   = g_s[b * L_ + idx] + mask[(size_t)bl * KK_ + tid];
        ish[tid]  = idx;
        float mx = s;
        #pragma unroll
        for (int o = 16; o; o >>= 1)
            mx = fmaxf(mx, __shfl_xor_sync(0xFFFFFFFFu, mx, o));
        float e = expf(s - mx);
        float sum = e;
        #pragma unroll
        for (int o = 16; o; o >>= 1)
            sum += __shfl_xor_sync(0xFFFFFFFFu, sum, o);
        wsh[tid] = e / sum;
    }
    __syncthreads();

    // each thread: 4 consecutive h = tid*4..tid*4+3 (one uint2 = 4 bf16 per row)
    const uint2* vh = reinterpret_cast<const uint2*>(g_vh);
    float4 acc = make_float4(0.f, 0.f, 0.f, 0.f);
    #pragma unroll 8
    for (int k = 0; k < KK_; k++) {
        float wk = wsh[k];
        uint2 u  = vh[((size_t)(b * L_ + ish[k])) * (H_ / 4) + tid];
        __nv_bfloat162 p0 = *reinterpret_cast<__nv_bfloat162*>(&u.x);
        __nv_bfloat162 p1 = *reinterpret_cast<__nv_bfloat162*>(&u.y);
        float2 f0 = __bfloat1622float2(p0);
        float2 f1 = __bfloat1622float2(p1);
        acc.x += wk * f0.x;
        acc.y += wk * f0.y;
        acc.z += wk * f1.x;
        acc.w += wk * f1.y;
    }
    acc.x = tf32r(acc.x); acc.y = tf32r(acc.y);
    acc.z = tf32r(acc.z); acc.w = tf32r(acc.w);
    reinterpret_cast<float4*>(g_attn)[(size_t)bl * (H_ / 4) + tid] = acc;
}

// ---------------- (10) layernorm ----------------
__global__ __launch_bounds__(128) void ln_kernel(
    const float* __restrict__ gma, const float* __restrict__ bta,
    float* __restrict__ out)
{
    const int row = blockIdx.x;
    const int tid = threadIdx.x;
    const float4 v = reinterpret_cast<const float4*>(g_x)[(size_t)row * (H_ / 4) + tid];

    float s  = v.x + v.y + v.z + v.w;
    float ss = v.x * v.x + v.y * v.y + v.z * v.z + v.w * v.w;
    #pragma unroll
    for (int o = 16; o; o >>= 1) {
        s  += __shfl_xor_sync(0xFFFFFFFFu, s, o);
        ss += __shfl_xor_sync(0xFFFFFFFFu, ss, o);
    }
    __shared__ float sh[8];
    int wid = tid >> 5, lane = tid & 31;
    if (lane == 0) { sh[wid] = s; sh[4 + wid] = ss; }
    __syncthreads();
    if (tid == 0) {
        float S  = sh[0] + sh[1] + sh[2] + sh[3];
        float SS = sh[4] + sh[5] + sh[6] + sh[7];
        sh[0] = S; sh[1] = SS;
    }
    __syncthreads();
    float mu  = sh[0] * (1.f / 512.f);
    float var = sh[1] * (1.f / 512.f) - mu * mu;
    float inv = rsqrtf(var + 1e-12f);

    float4 g4 = reinterpret_cast<const float4*>(gma)[tid];
    float4 b4 = reinterpret_cast<const float4*>(bta)[tid];
    float4 o;
    o.x = (v.x - mu) * inv * g4.x + b4.x;
    o.y = (v.y - mu) * inv * g4.y + b4.y;
    o.z = (v.z - mu) * inv * g4.z + b4.z;
    o.w = (v.w - mu) * inv * g4.w + b4.w;
    reinterpret_cast<float4*>(out)[(size_t)row * (H_ / 4) + tid] = o;
}

// ---------------- launch ----------------
extern "C" void kernel_launch(void* const* d_in, const int* in_sizes, int n_in,
                              void* d_out, int out_size)
{
    const float* user  = (const float*)d_in[0];
    const float* item  = (const float*)d_in[1];
    const float* mask  = (const float*)d_in[2];
    const void*  indexp =               d_in[3];
    const float* Wq    = (const float*)d_in[4];
    const float* bq    = (const float*)d_in[5];
    const float* Wk    = (const float*)d_in[6];
    const float* bk    = (const float*)d_in[7];
    const float* Wv    = (const float*)d_in[8];
    const float* bv    = (const float*)d_in[9];
    const float* Wd    = (const float*)d_in[10];
    const float* bd    = (const float*)d_in[11];
    const float* lng   = (const float*)d_in[12];
    const float* lnb   = (const float*)d_in[13];
    float* out = (float*)d_out;

    float *kp, *attnp, *xp, *itemc, *wfuse, *wdc, *bfuse;
    __nv_bfloat16* vhp;
    cudaGetSymbolAddress((void**)&kp,    g_k);
    cudaGetSymbolAddress((void**)&vhp,   g_vh);
    cudaGetSymbolAddress((void**)&attnp, g_attn);
    cudaGetSymbolAddress((void**)&xp,    g_x);
    cudaGetSymbolAddress((void**)&itemc, g_itemc);
    cudaGetSymbolAddress((void**)&wfuse, g_wfuse);
    cudaGetSymbolAddress((void**)&wdc,   g_wdc);
    cudaGetSymbolAddress((void**)&bfuse, g_bfuse);

    cudaFuncSetAttribute(gemm_tc_kernel, cudaFuncAttributeMaxDynamicSharedMemorySize, GS_SMEM);

    // (1,2) index normalization
    detect_kernel<<<1, 32>>>((const unsigned int*)indexp);
    convert_kernel<<<(L_ * KK_ + 255) / 256, 256>>>(indexp);

    // (3) round item, (4) round weights + pack biases, (5) qproj
    round_item_kernel<<<(BL_ * H_ / 4 + 255) / 256, 256>>>(item, itemc, BL_ * H_ / 4);
    round_w_kernel<<<(3 * WQ4 + 256 + 255) / 256, 256>>>(Wk, Wv, Wd, bk, bv);
    qproj_kernel<<<(B_ * H_) / 8, 256>>>(user, Wq, bq);

    // (6) fused K|V projection on tensor cores (profiled launch)
    dim3 gkv(1024 / 128, BL_ / 128);   // (8, 128)
    gemm_tc_kernel<<<gkv, 128, GS_SMEM>>>(itemc, wfuse, bfuse, nullptr, kp, vhp, 1);

    // (7) scores
    score_kernel<<<BL_ / 8, 256>>>();

    // (8) gather + softmax + weighted sum
    attn_kernel<<<BL_, 128>>>(mask);

    // (9) dense = attn @ Wd^T + bd + item
    dim3 gd(H_ / 128, BL_ / 128);      // (4, 128)
    gemm_tc_kernel<<<gd, 128, GS_SMEM>>>(attnp, wdc, bd, item, xp, nullptr, 0);

    // (10) layernorm -> out
    ln_kernel<<<BL_, 128>>>(lng, lnb, out);
}

// round 6
// speedup vs baseline: 2.7933x; 1.0391x over previous
#include <cuda_runtime.h>
#include <cuda_bf16.h>
#include <math.h>
#include <stdint.h>

#define B_  16
#define L_  1024
#define H_  512
#define KK_ 32
#define BL_ (B_ * L_)          // 16384
#define INVSQ 0.04419417382415922f

// ---------------- scratch (no allocations allowed) ----------------
__device__ float g_q[B_ * H_];
__device__ float g_p[B_ * H_];             // Wk^T q (pre-scaled)
__device__ float g_qbk[B_];                // q . bk (pre-scaled)
__device__ __nv_bfloat16 g_vh[BL_ * H_];   // V in bf16
__device__ float g_s[B_ * L_];
__device__ float g_attn[BL_ * H_];
__device__ float g_x[BL_ * H_];
__device__ float g_itemc[BL_ * H_];        // tf32-rounded item
__device__ float g_wvc[H_ * H_];           // tf32-rounded Wv
__device__ float g_wdc[H_ * H_];           // tf32-rounded Wd
__device__ int   g_index[L_ * KK_];
__device__ int   g_is64;

__device__ __forceinline__ float tf32r(float x) {
    uint32_t u;
    asm("cvt.rna.tf32.f32 %0, %1;" : "=r"(u) : "f"(x));
    return __uint_as_float(u);
}
__device__ __forceinline__ void cp16(uint32_t d, const void* g) {
    asm volatile("cp.async.cg.shared.global [%0], [%1], 16;" :: "r"(d), "l"(g));
}
__device__ __forceinline__ uint32_t smem_u32(const void* p) {
    uint32_t a;
    asm("{ .reg .u64 t; cvta.to.shared.u64 t, %1; cvt.u32.u64 %0, t; }" : "=r"(a) : "l"(p));
    return a;
}
__device__ __forceinline__ void mma_tf32(float* d, const uint32_t* a, const uint32_t* b) {
    asm volatile(
        "mma.sync.aligned.m16n8k8.row.col.f32.tf32.tf32.f32 "
        "{%0,%1,%2,%3}, {%4,%5,%6,%7}, {%8,%9}, {%0,%1,%2,%3};"
        : "+f"(d[0]), "+f"(d[1]), "+f"(d[2]), "+f"(d[3])
        : "r"(a[0]), "r"(a[1]), "r"(a[2]), "r"(a[3]), "r"(b[0]), "r"(b[1]));
}

// ---------------- (1) index dtype detection ----------------
__global__ void detect_kernel(const unsigned int* __restrict__ w) {
    unsigned int any = 0;
    for (int i = threadIdx.x; i < 1024; i += 32)
        any |= w[2 * i + 1];
    #pragma unroll
    for (int o = 16; o; o >>= 1)
        any |= __shfl_xor_sync(0xFFFFFFFFu, any, o);
    if (threadIdx.x == 0) g_is64 = (any == 0u) ? 1 : 0;
}

// ---------------- (2) index normalization ----------------
__global__ void convert_kernel(const void* __restrict__ idx) {
    int i = blockIdx.x * blockDim.x + threadIdx.x;
    if (i >= L_ * KK_) return;
    if (g_is64) g_index[i] = (int)((const long long*)idx)[i];
    else        g_index[i] = ((const int*)idx)[i];
}

// ---------------- (3) tf32 round of item ----------------
__global__ __launch_bounds__(256) void round_item_kernel(
    const float* __restrict__ in, float* __restrict__ out, int n4)
{
    int i = blockIdx.x * blockDim.x + threadIdx.x;
    if (i >= n4) return;
    float4 v = reinterpret_cast<const float4*>(in)[i];
    v.x = tf32r(v.x); v.y = tf32r(v.y); v.z = tf32r(v.z); v.w = tf32r(v.w);
    reinterpret_cast<float4*>(out)[i] = v;
}

// ---------------- (4) round Wv, Wd ----------------
#define WQ4 (H_ * H_ / 4)
__global__ __launch_bounds__(256) void round_w_kernel(
    const float* __restrict__ Wv, const float* __restrict__ Wd)
{
    int i = blockIdx.x * blockDim.x + threadIdx.x;
    if (i >= 2 * WQ4) return;
    const float* src; float* dst; int j = i;
    if (i < WQ4) { src = Wv; dst = g_wvc; }
    else         { src = Wd; dst = g_wdc; j -= WQ4; }
    float4 v = reinterpret_cast<const float4*>(src)[j];
    v.x = tf32r(v.x); v.y = tf32r(v.y); v.z = tf32r(v.z); v.w = tf32r(v.w);
    reinterpret_cast<float4*>(dst)[j] = v;
}

// ---------------- (5) q projection (fp32) ----------------
__global__ __launch_bounds__(256) void qproj_kernel(
    const float* __restrict__ user, const float* __restrict__ Wq,
    const float* __restrict__ bq)
{
    int o    = (blockIdx.x * blockDim.x + threadIdx.x) >> 5;
    int lane = threadIdx.x & 31;
    int b = o >> 9;
    int n = o & 511;
    const float4* u4 = reinterpret_cast<const float4*>(user + (size_t)b * H_);
    const float4* w4 = reinterpret_cast<const float4*>(Wq + (size_t)n * H_);
    float acc = 0.f;
    #pragma unroll
    for (int i = lane; i < H_ / 4; i += 32) {
        float4 a = u4[i], w = w4[i];
        acc += a.x * w.x + a.y * w.y + a.z * w.z + a.w * w.w;
    }
    #pragma unroll
    for (int off = 16; off; off >>= 1)
        acc += __shfl_xor_sync(0xFFFFFFFFu, acc, off);
    if (lane == 0) g_q[o] = acc + bq[n];
}

// ---------------- (6) p[b] = Wk^T q[b] (pre-scaled), qbk[b] = q.bk ----------------
__global__ __launch_bounds__(128) void pk_kernel(
    const float* __restrict__ Wk, const float* __restrict__ bk)
{
    const int b  = blockIdx.y;
    const int j  = blockIdx.x * 128 + threadIdx.x;
    const int tid = threadIdx.x;
    __shared__ float qs[H_];
    __shared__ float red[128];
    for (int i = tid; i < H_; i += 128) qs[i] = g_q[b * H_ + i];
    __syncthreads();

    float acc = 0.f;
    #pragma unroll 8
    for (int i = 0; i < H_; i++)
        acc += Wk[(size_t)i * H_ + j] * qs[i];
    g_p[b * H_ + j] = acc * INVSQ;

    if (blockIdx.x == 0) {
        float a = 0.f;
        for (int i = tid; i < H_; i += 128) a += qs[i] * bk[i];
        red[tid] = a;
        __syncthreads();
        #pragma unroll
        for (int s = 64; s; s >>= 1) {
            if (tid < s) red[tid] += red[tid + s];
            __syncthreads();
        }
        if (tid == 0) g_qbk[b] = red[0] * INVSQ;
    }
}

// ---------------- (7) scores: s[b,l] = p[b].item[b,l] + qbk[b] ----------------
__global__ __launch_bounds__(256) void score_kernel(const float* __restrict__ item) {
    int w    = (blockIdx.x * blockDim.x + threadIdx.x) >> 5;   // 0..16383
    int lane = threadIdx.x & 31;
    int b = w >> 10;
    const float4* ir = reinterpret_cast<const float4*>(item + (size_t)w * H_);
    const float4* pr = reinterpret_cast<const float4*>(g_p + (size_t)b * H_);
    float acc = 0.f;
    #pragma unroll
    for (int i = lane; i < H_ / 4; i += 32) {
        float4 a = ir[i], p = pr[i];
        acc += a.x * p.x + a.y * p.y + a.z * p.z + a.w * p.w;
    }
    #pragma unroll
    for (int off = 16; off; off >>= 1)
        acc += __shfl_xor_sync(0xFFFFFFFFu, acc, off);
    if (lane == 0) g_s[w] = acc + g_qbk[b];
}

// ================= tf32 mma.sync GEMM =================
// CTA tile 128x128, 4 warps (warp 64x64), BK=32, 3-stage cp.async ring.
// mode 0: Cf = A@W^T + bias + addend (fp32). mode 1: Cv = bf16(A@W^T + bias).
#define GS_STRIDE 36
#define GS_TILE   (128 * GS_STRIDE)
#define GS_SLOT   (2 * GS_TILE)
#define GS_SMEM   (3 * GS_SLOT * 4)               // 110592 bytes

__global__ void __launch_bounds__(128) gemm_tc_kernel(
    const float* __restrict__ A, const float* __restrict__ W,
    const float* __restrict__ bias, const float* __restrict__ addend,
    float* __restrict__ Cf, __nv_bfloat16* __restrict__ Cv, int mode)
{
    extern __shared__ float sm[];

    const int tid  = threadIdx.x;
    const int lane = tid & 31;
    const int warp = tid >> 5;
    const int wm   = (warp & 1) * 64;
    const int wn   = (warp >> 1) * 64;
    const int g    = lane >> 2;
    const int t    = lane & 3;
    const int bm   = blockIdx.y * 128;
    const int bn   = blockIdx.x * 128;

    const int lrow = tid >> 3;
    const int lc   = tid & 7;

    const float* Abase = A + (size_t)bm * H_ + lc * 4;
    const float* Bbase = W + (size_t)bn * H_ + lc * 4;

    float acc[4][8][4];
    #pragma unroll
    for (int mi = 0; mi < 4; mi++)
        #pragma unroll
        for (int ni = 0; ni < 8; ni++)
            #pragma unroll
            for (int r = 0; r < 4; r++) acc[mi][ni][r] = 0.f;

    const uint32_t smb = smem_u32(sm);
    const int NST = H_ / 32;   // 16

    #pragma unroll
    for (int p = 0; p < 2; p++) {
        const uint32_t ab = smb + (uint32_t)(p * GS_SLOT) * 4;
        const uint32_t bb = ab + GS_TILE * 4;
        const int k0 = p * 32;
        #pragma unroll
        for (int i = 0; i < 8; i++) {
            int row = lrow + i * 16;
            uint32_t off = (uint32_t)(row * GS_STRIDE + lc * 4) * 4;
            cp16(ab + off, Abase + (size_t)row * H_ + k0);
            cp16(bb + off, Bbase + (size_t)row * H_ + k0);
        }
        asm volatile("cp.async.commit_group;" ::: "memory");
    }

    for (int s = 0; s < NST; s++) {
        if (s < NST - 1) asm volatile("cp.async.wait_group 1;" ::: "memory");
        else             asm volatile("cp.async.wait_group 0;" ::: "memory");
        __syncthreads();

        if (s + 2 < NST) {
            const int slot = (s + 2) % 3;
            const uint32_t ab = smb + (uint32_t)(slot * GS_SLOT) * 4;
            const uint32_t bb = ab + GS_TILE * 4;
            const int k0 = (s + 2) * 32;
            #pragma unroll
            for (int i = 0; i < 8; i++) {
                int row = lrow + i * 16;
                uint32_t off = (uint32_t)(row * GS_STRIDE + lc * 4) * 4;
                cp16(ab + off, Abase + (size_t)row * H_ + k0);
                cp16(bb + off, Bbase + (size_t)row * H_ + k0);
            }
            asm volatile("cp.async.commit_group;" ::: "memory");
        }

        const float* slotp = sm + (s % 3) * GS_SLOT;
        const uint32_t* Au = reinterpret_cast<const uint32_t*>(slotp);
        const uint32_t* Bu = reinterpret_cast<const uint32_t*>(slotp + GS_TILE);
        #pragma unroll
        for (int kk = 0; kk < 4; kk++) {
            const int k = kk * 8;
            uint32_t af[4][4], bf[8][2];
            #pragma unroll
            for (int mi = 0; mi < 4; mi++) {
                int row = wm + mi * 16 + g;
                af[mi][0] = Au[row * GS_STRIDE + k + t];
                af[mi][1] = Au[(row + 8) * GS_STRIDE + k + t];
                af[mi][2] = Au[row * GS_STRIDE + k + t + 4];
                af[mi][3] = Au[(row + 8) * GS_STRIDE + k + t + 4];
            }
            #pragma unroll
            for (int ni = 0; ni < 8; ni++) {
                int col = wn + ni * 8 + g;
                bf[ni][0] = Bu[col * GS_STRIDE + k + t];
                bf[ni][1] = Bu[col * GS_STRIDE + k + t + 4];
            }
            #pragma unroll
            for (int mi = 0; mi < 4; mi++)
                #pragma unroll
                for (int ni = 0; ni < 8; ni++)
                    mma_tf32(acc[mi][ni], af[mi], bf[ni]);
        }
    }

    // ---- epilogue ----
    #pragma unroll
    for (int mi = 0; mi < 4; mi++) {
        const int m0 = bm + wm + mi * 16 + g;
        #pragma unroll
        for (int ni = 0; ni < 8; ni++) {
            const int n = bn + wn + ni * 8 + 2 * t;
            float2 bs = *reinterpret_cast<const float2*>(bias + n);
            float2 o0, o1;
            o0.x = acc[mi][ni][0] + bs.x;
            o0.y = acc[mi][ni][1] + bs.y;
            o1.x = acc[mi][ni][2] + bs.x;
            o1.y = acc[mi][ni][3] + bs.y;
            if (mode == 0) {
                float2 a0 = *reinterpret_cast<const float2*>(addend + (size_t)m0 * H_ + n);
                float2 a1 = *reinterpret_cast<const float2*>(addend + (size_t)(m0 + 8) * H_ + n);
                o0.x += a0.x; o0.y += a0.y;
                o1.x += a1.x; o1.y += a1.y;
                *reinterpret_cast<float2*>(Cf + (size_t)m0 * H_ + n)       = o0;
                *reinterpret_cast<float2*>(Cf + (size_t)(m0 + 8) * H_ + n) = o1;
            } else {
                *reinterpret_cast<__nv_bfloat162*>(Cv + (size_t)m0 * H_ + n) =
                    __floats2bfloat162_rn(o0.x, o0.y);
                *reinterpret_cast<__nv_bfloat162*>(Cv + (size_t)(m0 + 8) * H_ + n) =
                    __floats2bfloat162_rn(o1.x, o1.y);
            }
        }
    }
}

// ---------------- (9) gather + softmax + weighted bf16-V sum ----------------
__global__ __launch_bounds__(128) void attn_kernel(const float* __restrict__ mask) {
    __shared__ float wsh[KK_];
    __shared__ int   ish[KK_];
    const int bl  = blockIdx.x;
    const int b   = bl >> 10;
    const int l   = bl & 1023;
    const int tid = threadIdx.x;

    if (tid < KK_) {
        int   idx = g_index[l * KK_ + tid];
        float s   = g_s[b * L_ + idx] + mask[(size_t)bl * KK_ + tid];
        ish[tid]  = idx;
        float mx = s;
        #pragma unroll
        for (int o = 16; o; o >>= 1)
            mx = fmaxf(mx, __shfl_xor_sync(0xFFFFFFFFu, mx, o));
        float e = expf(s - mx);
        float sum = e;
        #pragma unroll
        for (int o = 16; o; o >>= 1)
            sum += __shfl_xor_sync(0xFFFFFFFFu, sum, o);
        wsh[tid] = e / sum;
    }
    __syncthreads();

    const uint2* vh = reinterpret_cast<const uint2*>(g_vh);
    float4 acc = make_float4(0.f, 0.f, 0.f, 0.f);
    #pragma unroll 8
    for (int k = 0; k < KK_; k++) {
        float wk = wsh[k];
        uint2 u  = vh[((size_t)(b * L_ + ish[k])) * (H_ / 4) + tid];
        __nv_bfloat162 p0 = *reinterpret_cast<__nv_bfloat162*>(&u.x);
        __nv_bfloat162 p1 = *reinterpret_cast<__nv_bfloat162*>(&u.y);
        float2 f0 = __bfloat1622float2(p0);
        float2 f1 = __bfloat1622float2(p1);
        acc.x += wk * f0.x;
        acc.y += wk * f0.y;
        acc.z += wk * f1.x;
        acc.w += wk * f1.y;
    }
    acc.x = tf32r(acc.x); acc.y = tf32r(acc.y);
    acc.z = tf32r(acc.z); acc.w = tf32r(acc.w);
    reinterpret_cast<float4*>(g_attn)[(size_t)bl * (H_ / 4) + tid] = acc;
}

// ---------------- (11) layernorm ----------------
__global__ __launch_bounds__(128) void ln_kernel(
    const float* __restrict__ gma, const float* __restrict__ bta,
    float* __restrict__ out)
{
    const int row = blockIdx.x;
    const int tid = threadIdx.x;
    const float4 v = reinterpret_cast<const float4*>(g_x)[(size_t)row * (H_ / 4) + tid];

    float s  = v.x + v.y + v.z + v.w;
    float ss = v.x * v.x + v.y * v.y + v.z * v.z + v.w * v.w;
    #pragma unroll
    for (int o = 16; o; o >>= 1) {
        s  += __shfl_xor_sync(0xFFFFFFFFu, s, o);
        ss += __shfl_xor_sync(0xFFFFFFFFu, ss, o);
    }
    __shared__ float sh[8];
    int wid = tid >> 5, lane = tid & 31;
    if (lane == 0) { sh[wid] = s; sh[4 + wid] = ss; }
    __syncthreads();
    if (tid == 0) {
        float S  = sh[0] + sh[1] + sh[2] + sh[3];
        float SS = sh[4] + sh[5] + sh[6] + sh[7];
        sh[0] = S; sh[1] = SS;
    }
    __syncthreads();
    float mu  = sh[0] * (1.f / 512.f);
    float var = sh[1] * (1.f / 512.f) - mu * mu;
    float inv = rsqrtf(var + 1e-12f);

    float4 g4 = reinterpret_cast<const float4*>(gma)[tid];
    float4 b4 = reinterpret_cast<const float4*>(bta)[tid];
    float4 o;
    o.x = (v.x - mu) * inv * g4.x + b4.x;
    o.y = (v.y - mu) * inv * g4.y + b4.y;
    o.z = (v.z - mu) * inv * g4.z + b4.z;
    o.w = (v.w - mu) * inv * g4.w + b4.w;
    reinterpret_cast<float4*>(out)[(size_t)row * (H_ / 4) + tid] = o;
}

// ---------------- launch ----------------
extern "C" void kernel_launch(void* const* d_in, const int* in_sizes, int n_in,
                              void* d_out, int out_size)
{
    const float* user  = (const float*)d_in[0];
    const float* item  = (const float*)d_in[1];
    const float* mask  = (const float*)d_in[2];
    const void*  indexp =               d_in[3];
    const float* Wq    = (const float*)d_in[4];
    const float* bq    = (const float*)d_in[5];
    const float* Wk    = (const float*)d_in[6];
    const float* bk    = (const float*)d_in[7];
    const float* Wv    = (const float*)d_in[8];
    const float* bv    = (const float*)d_in[9];
    const float* Wd    = (const float*)d_in[10];
    const float* bd    = (const float*)d_in[11];
    const float* lng   = (const float*)d_in[12];
    const float* lnb   = (const float*)d_in[13];
    float* out = (float*)d_out;

    float *attnp, *xp, *itemc, *wvc, *wdc;
    __nv_bfloat16* vhp;
    cudaGetSymbolAddress((void**)&vhp,   g_vh);
    cudaGetSymbolAddress((void**)&attnp, g_attn);
    cudaGetSymbolAddress((void**)&xp,    g_x);
    cudaGetSymbolAddress((void**)&itemc, g_itemc);
    cudaGetSymbolAddress((void**)&wvc,   g_wvc);
    cudaGetSymbolAddress((void**)&wdc,   g_wdc);

    cudaFuncSetAttribute(gemm_tc_kernel, cudaFuncAttributeMaxDynamicSharedMemorySize, GS_SMEM);

    // (1,2) index normalization
    detect_kernel<<<1, 32>>>((const unsigned int*)indexp);
    convert_kernel<<<(L_ * KK_ + 255) / 256, 256>>>(indexp);

    // (3,4,5) pre-rounding + q projection
    round_item_kernel<<<(BL_ * H_ / 4 + 255) / 256, 256>>>(item, itemc, BL_ * H_ / 4);
    round_w_kernel<<<(2 * WQ4 + 255) / 256, 256>>>(Wv, Wd);
    qproj_kernel<<<(B_ * H_) / 8, 256>>>(user, Wq, bq);

    // (6) p = Wk^T q (kills the K GEMM)
    pk_kernel<<<dim3(H_ / 128, B_), 128>>>(Wk, bk);

    // (7) scores from item directly (full fp32)
    score_kernel<<<BL_ / 8, 256>>>(item);

    // (8) V projection on tensor cores -> bf16
    dim3 gv(H_ / 128, BL_ / 128);      // (4, 128)
    gemm_tc_kernel<<<gv, 128, GS_SMEM>>>(itemc, wvc, bv, nullptr, nullptr, vhp, 1);

    // (9) gather + softmax + weighted sum
    attn_kernel<<<BL_, 128>>>(mask);

    // (10) dense = attn @ Wd^T + bd + item
    gemm_tc_kernel<<<gv, 128, GS_SMEM>>>(attnp, wdc, bd, item, xp, nullptr, 0);

    // (11) layernorm -> out
    ln_kernel<<<BL_, 128>>>(lng, lnb, out);
}

// round 7
// speedup vs baseline: 3.6461x; 1.3053x over previous
#include <cuda_runtime.h>
#include <cuda_fp16.h>
#include <math.h>
#include <stdint.h>

#define B_  16
#define L_  1024
#define H_  512
#define KK_ 32
#define BL_ (B_ * L_)          // 16384
#define INVSQ 0.04419417382415922f

// ---------------- scratch (no allocations allowed) ----------------
__device__ float  g_q[B_ * H_];
__device__ float  g_p[B_ * H_];            // Wk^T q (pre-scaled)
__device__ float  g_qbk[B_];               // q . bk (pre-scaled)
__device__ __half g_vh[BL_ * H_];          // V in fp16
__device__ float  g_s[B_ * L_];
__device__ __half g_attnh[BL_ * H_];       // attn out in fp16 (dense GEMM A)
__device__ float  g_x[BL_ * H_];
__device__ __half g_itemh[BL_ * H_];       // fp16 item (GEMM A)
__device__ __half g_wvh[H_ * H_];          // fp16 Wv
__device__ __half g_wdh[H_ * H_];          // fp16 Wd
__device__ int    g_index[L_ * KK_];
__device__ int    g_is64;

__device__ __forceinline__ void cp16(uint32_t d, const void* g) {
    asm volatile("cp.async.cg.shared.global [%0], [%1], 16;" :: "r"(d), "l"(g));
}
__device__ __forceinline__ uint32_t smem_u32(const void* p) {
    uint32_t a;
    asm("{ .reg .u64 t; cvta.to.shared.u64 t, %1; cvt.u32.u64 %0, t; }" : "=r"(a) : "l"(p));
    return a;
}
__device__ __forceinline__ void mma_f16(float* d, const uint32_t* a, const uint32_t* b) {
    asm volatile(
        "mma.sync.aligned.m16n8k16.row.col.f32.f16.f16.f32 "
        "{%0,%1,%2,%3}, {%4,%5,%6,%7}, {%8,%9}, {%0,%1,%2,%3};"
        : "+f"(d[0]), "+f"(d[1]), "+f"(d[2]), "+f"(d[3])
        : "r"(a[0]), "r"(a[1]), "r"(a[2]), "r"(a[3]), "r"(b[0]), "r"(b[1]));
}

// ---------------- (1) index dtype detection ----------------
__global__ void detect_kernel(const unsigned int* __restrict__ w) {
    unsigned int any = 0;
    for (int i = threadIdx.x; i < 1024; i += 32)
        any |= w[2 * i + 1];
    #pragma unroll
    for (int o = 16; o; o >>= 1)
        any |= __shfl_xor_sync(0xFFFFFFFFu, any, o);
    if (threadIdx.x == 0) g_is64 = (any == 0u) ? 1 : 0;
}

// ---------------- (2) index normalization ----------------
__global__ void convert_kernel(const void* __restrict__ idx) {
    int i = blockIdx.x * blockDim.x + threadIdx.x;
    if (i >= L_ * KK_) return;
    if (g_is64) g_index[i] = (int)((const long long*)idx)[i];
    else        g_index[i] = ((const int*)idx)[i];
}

// ---------------- (3) fp16 conversion: item, Wv, Wd (one launch) ----------------
#define ITEM4 (BL_ * H_ / 4)   // 2097152
#define WQ4   (H_ * H_ / 4)    // 65536
__global__ __launch_bounds__(256) void to_half_kernel(
    const float* __restrict__ item, const float* __restrict__ Wv,
    const float* __restrict__ Wd)
{
    int i = blockIdx.x * blockDim.x + threadIdx.x;
    const float* src; __half* dst; int j = i;
    if (i < ITEM4)                 { src = item; dst = g_itemh; }
    else if (i < ITEM4 + WQ4)      { src = Wv;   dst = g_wvh; j -= ITEM4; }
    else if (i < ITEM4 + 2 * WQ4)  { src = Wd;   dst = g_wdh; j -= ITEM4 + WQ4; }
    else return;
    float4 v = reinterpret_cast<const float4*>(src)[j];
    uint2 o;
    *reinterpret_cast<__half2*>(&o.x) = __floats2half2_rn(v.x, v.y);
    *reinterpret_cast<__half2*>(&o.y) = __floats2half2_rn(v.z, v.w);
    reinterpret_cast<uint2*>(dst)[j] = o;
}

// ---------------- (4) q projection (fp32) ----------------
__global__ __launch_bounds__(256) void qproj_kernel(
    const float* __restrict__ user, const float* __restrict__ Wq,
    const float* __restrict__ bq)
{
    int o    = (blockIdx.x * blockDim.x + threadIdx.x) >> 5;
    int lane = threadIdx.x & 31;
    int b = o >> 9;
    int n = o & 511;
    const float4* u4 = reinterpret_cast<const float4*>(user + (size_t)b * H_);
    const float4* w4 = reinterpret_cast<const float4*>(Wq + (size_t)n * H_);
    float acc = 0.f;
    #pragma unroll
    for (int i = lane; i < H_ / 4; i += 32) {
        float4 a = u4[i], w = w4[i];
        acc += a.x * w.x + a.y * w.y + a.z * w.z + a.w * w.w;
    }
    #pragma unroll
    for (int off = 16; off; off >>= 1)
        acc += __shfl_xor_sync(0xFFFFFFFFu, acc, off);
    if (lane == 0) g_q[o] = acc + bq[n];
}

// ---------------- (5) p[b] = Wk^T q[b] (pre-scaled), qbk[b] = q.bk ----------------
__global__ __launch_bounds__(128) void pk_kernel(
    const float* __restrict__ Wk, const float* __restrict__ bk)
{
    const int b  = blockIdx.y;
    const int j  = blockIdx.x * 128 + threadIdx.x;
    const int tid = threadIdx.x;
    __shared__ float qs[H_];
    __shared__ float red[128];
    for (int i = tid; i < H_; i += 128) qs[i] = g_q[b * H_ + i];
    __syncthreads();

    float acc = 0.f;
    #pragma unroll 8
    for (int i = 0; i < H_; i++)
        acc += Wk[(size_t)i * H_ + j] * qs[i];
    g_p[b * H_ + j] = acc * INVSQ;

    if (blockIdx.x == 0) {
        float a = 0.f;
        for (int i = tid; i < H_; i += 128) a += qs[i] * bk[i];
        red[tid] = a;
        __syncthreads();
        #pragma unroll
        for (int s = 64; s; s >>= 1) {
            if (tid < s) red[tid] += red[tid + s];
            __syncthreads();
        }
        if (tid == 0) g_qbk[b] = red[0] * INVSQ;
    }
}

// ---------------- (6) scores: s[b,l] = p[b].item[b,l] + qbk[b] ----------------
__global__ __launch_bounds__(256) void score_kernel(const float* __restrict__ item) {
    int w    = (blockIdx.x * blockDim.x + threadIdx.x) >> 5;
    int lane = threadIdx.x & 31;
    int b = w >> 10;
    const float4* ir = reinterpret_cast<const float4*>(item + (size_t)w * H_);
    const float4* pr = reinterpret_cast<const float4*>(g_p + (size_t)b * H_);
    float acc = 0.f;
    #pragma unroll
    for (int i = lane; i < H_ / 4; i += 32) {
        float4 a = ir[i], p = pr[i];
        acc += a.x * p.x + a.y * p.y + a.z * p.z + a.w * p.w;
    }
    #pragma unroll
    for (int off = 16; off; off >>= 1)
        acc += __shfl_xor_sync(0xFFFFFFFFu, acc, off);
    if (lane == 0) g_s[w] = acc + g_qbk[b];
}

// ================= fp16 mma.sync GEMM =================
// C[m,n] = sum_k A[m,k] * W[n,k] (+ bias[n]) (+ addend fp32)
// CTA 128x128, 4 warps (warp 64x64), BK=32, m16n8k16, 3-stage cp.async ring.
// smem row stride 40 halves (80B). 2 CTAs/SM.
// mode 0: Cf = fp32 out + bias + addend.  mode 1: Ch = fp16(out + bias).
#define GH_STRIDE 40
#define GH_TILE   (128 * GH_STRIDE)            // halves per matrix stage (5120)
#define GH_SLOT   (2 * GH_TILE)                // A+B per slot (10240 halves)
#define GH_SMEM   (3 * GH_SLOT * 2)            // 61440 bytes

__global__ void __launch_bounds__(128) gemm_h_kernel(
    const __half* __restrict__ A, const __half* __restrict__ W,
    const float* __restrict__ bias, const float* __restrict__ addend,
    float* __restrict__ Cf, __half* __restrict__ Ch, int mode)
{
    extern __shared__ __half smh[];

    const int tid  = threadIdx.x;
    const int lane = tid & 31;
    const int warp = tid >> 5;
    const int wm   = (warp & 1) * 64;
    const int wn   = (warp >> 1) * 64;
    const int g    = lane >> 2;
    const int t    = lane & 3;
    const int bm   = blockIdx.y * 128;
    const int bn   = blockIdx.x * 128;

    const int lrow = tid >> 2;             // 0..31 (+32 per i)
    const int lc   = tid & 3;              // 16B chunk (8 halves)

    const __half* Abase = A + (size_t)bm * H_ + lc * 8;
    const __half* Bbase = W + (size_t)bn * H_ + lc * 8;

    float acc[4][8][4];
    #pragma unroll
    for (int mi = 0; mi < 4; mi++)
        #pragma unroll
        for (int ni = 0; ni < 8; ni++)
            #pragma unroll
            for (int r = 0; r < 4; r++) acc[mi][ni][r] = 0.f;

    const uint32_t smb = smem_u32(smh);
    const int NST = H_ / 32;   // 16

    // prologue: stages 0,1
    #pragma unroll
    for (int p = 0; p < 2; p++) {
        const uint32_t ab = smb + (uint32_t)(p * GH_SLOT) * 2;
        const uint32_t bb = ab + GH_TILE * 2;
        const int k0 = p * 32;
        #pragma unroll
        for (int i = 0; i < 4; i++) {
            int row = lrow + i * 32;
            uint32_t off = (uint32_t)(row * 80 + lc * 16);
            cp16(ab + off, Abase + (size_t)row * H_ + k0);
            cp16(bb + off, Bbase + (size_t)row * H_ + k0);
        }
        asm volatile("cp.async.commit_group;" ::: "memory");
    }

    for (int s = 0; s < NST; s++) {
        if (s < NST - 1) asm volatile("cp.async.wait_group 1;" ::: "memory");
        else             asm volatile("cp.async.wait_group 0;" ::: "memory");
        __syncthreads();

        if (s + 2 < NST) {
            const int slot = (s + 2) % 3;
            const uint32_t ab = smb + (uint32_t)(slot * GH_SLOT) * 2;
            const uint32_t bb = ab + GH_TILE * 2;
            const int k0 = (s + 2) * 32;
            #pragma unroll
            for (int i = 0; i < 4; i++) {
                int row = lrow + i * 32;
                uint32_t off = (uint32_t)(row * 80 + lc * 16);
                cp16(ab + off, Abase + (size_t)row * H_ + k0);
                cp16(bb + off, Bbase + (size_t)row * H_ + k0);
            }
            asm volatile("cp.async.commit_group;" ::: "memory");
        }

        const __half* slotp = smh + (s % 3) * GH_SLOT;
        const uint32_t* Au = reinterpret_cast<const uint32_t*>(slotp);
        const uint32_t* Bu = reinterpret_cast<const uint32_t*>(slotp + GH_TILE);
        #pragma unroll
        for (int kk = 0; kk < 2; kk++) {          // two k16 chunks per BK=32
            const int kw = kk * 8;                // uint32 offset within row
            uint32_t af[4][4], bf[8][2];
            #pragma unroll
            for (int mi = 0; mi < 4; mi++) {
                int row = wm + mi * 16 + g;
                af[mi][0] = Au[row * 20 + kw + t];
                af[mi][1] = Au[(row + 8) * 20 + kw + t];
                af[mi][2] = Au[row * 20 + kw + t + 4];
                af[mi][3] = Au[(row + 8) * 20 + kw + t + 4];
            }
            #pragma unroll
            for (int ni = 0; ni < 8; ni++) {
                int col = wn + ni * 8 + g;
                bf[ni][0] = Bu[col * 20 + kw + t];
                bf[ni][1] = Bu[col * 20 + kw + t + 4];
            }
            #pragma unroll
            for (int mi = 0; mi < 4; mi++)
                #pragma unroll
                for (int ni = 0; ni < 8; ni++)
                    mma_f16(acc[mi][ni], af[mi], bf[ni]);
        }
    }

    // ---- epilogue ----
    #pragma unroll
    for (int mi = 0; mi < 4; mi++) {
        const int m0 = bm + wm + mi * 16 + g;
        #pragma unroll
        for (int ni = 0; ni < 8; ni++) {
            const int n = bn + wn + ni * 8 + 2 * t;
            float2 bs = *reinterpret_cast<const float2*>(bias + n);
            float2 o0, o1;
            o0.x = acc[mi][ni][0] + bs.x;
            o0.y = acc[mi][ni][1] + bs.y;
            o1.x = acc[mi][ni][2] + bs.x;
            o1.y = acc[mi][ni][3] + bs.y;
            if (mode == 0) {
                float2 a0 = *reinterpret_cast<const float2*>(addend + (size_t)m0 * H_ + n);
                float2 a1 = *reinterpret_cast<const float2*>(addend + (size_t)(m0 + 8) * H_ + n);
                o0.x += a0.x; o0.y += a0.y;
                o1.x += a1.x; o1.y += a1.y;
                *reinterpret_cast<float2*>(Cf + (size_t)m0 * H_ + n)       = o0;
                *reinterpret_cast<float2*>(Cf + (size_t)(m0 + 8) * H_ + n) = o1;
            } else {
                *reinterpret_cast<__half2*>(Ch + (size_t)m0 * H_ + n) =
                    __floats2half2_rn(o0.x, o0.y);
                *reinterpret_cast<__half2*>(Ch + (size_t)(m0 + 8) * H_ + n) =
                    __floats2half2_rn(o1.x, o1.y);
            }
        }
    }
}

// ---------------- (8) gather + softmax + weighted fp16-V sum ----------------
__global__ __launch_bounds__(128) void attn_kernel(const float* __restrict__ mask) {
    __shared__ float wsh[KK_];
    __shared__ int   ish[KK_];
    const int bl  = blockIdx.x;
    const int b   = bl >> 10;
    const int l   = bl & 1023;
    const int tid = threadIdx.x;

    if (tid < KK_) {
        int   idx = g_index[l * KK_ + tid];
        float s   = g_s[b * L_ + idx] + mask[(size_t)bl * KK_ + tid];
        ish[tid]  = idx;
        float mx = s;
        #pragma unroll
        for (int o = 16; o; o >>= 1)
            mx = fmaxf(mx, __shfl_xor_sync(0xFFFFFFFFu, mx, o));
        float e = expf(s - mx);
        float sum = e;
        #pragma unroll
        for (int o = 16; o; o >>= 1)
            sum += __shfl_xor_sync(0xFFFFFFFFu, sum, o);
        wsh[tid] = e / sum;
    }
    __syncthreads();

    const uint2* vh = reinterpret_cast<const uint2*>(g_vh);
    float4 acc = make_float4(0.f, 0.f, 0.f, 0.f);
    #pragma unroll 8
    for (int k = 0; k < KK_; k++) {
        float wk = wsh[k];
        uint2 u  = vh[((size_t)(b * L_ + ish[k])) * (H_ / 4) + tid];
        float2 f0 = __half22float2(*reinterpret_cast<__half2*>(&u.x));
        float2 f1 = __half22float2(*reinterpret_cast<__half2*>(&u.y));
        acc.x += wk * f0.x;
        acc.y += wk * f0.y;
        acc.z += wk * f1.x;
        acc.w += wk * f1.y;
    }
    uint2 o;
    *reinterpret_cast<__half2*>(&o.x) = __floats2half2_rn(acc.x, acc.y);
    *reinterpret_cast<__half2*>(&o.y) = __floats2half2_rn(acc.z, acc.w);
    reinterpret_cast<uint2*>(g_attnh)[(size_t)bl * (H_ / 4) + tid] = o;
}

// ---------------- (10) layernorm ----------------
__global__ __launch_bounds__(128) void ln_kernel(
    const float* __restrict__ gma, const float* __restrict__ bta,
    float* __restrict__ out)
{
    const int row = blockIdx.x;
    const int tid = threadIdx.x;
    const float4 v = reinterpret_cast<const float4*>(g_x)[(size_t)row * (H_ / 4) + tid];

    float s  = v.x + v.y + v.z + v.w;
    float ss = v.x * v.x + v.y * v.y + v.z * v.z + v.w * v.w;
    #pragma unroll
    for (int o = 16; o; o >>= 1) {
        s  += __shfl_xor_sync(0xFFFFFFFFu, s, o);
        ss += __shfl_xor_sync(0xFFFFFFFFu, ss, o);
    }
    __shared__ float sh[8];
    int wid = tid >> 5, lane = tid & 31;
    if (lane == 0) { sh[wid] = s; sh[4 + wid] = ss; }
    __syncthreads();
    if (tid == 0) {
        float S  = sh[0] + sh[1] + sh[2] + sh[3];
        float SS = sh[4] + sh[5] + sh[6] + sh[7];
        sh[0] = S; sh[1] = SS;
    }
    __syncthreads();
    float mu  = sh[0] * (1.f / 512.f);
    float var = sh[1] * (1.f / 512.f) - mu * mu;
    float inv = rsqrtf(var + 1e-12f);

    float4 g4 = reinterpret_cast<const float4*>(gma)[tid];
    float4 b4 = reinterpret_cast<const float4*>(bta)[tid];
    float4 o;
    o.x = (v.x - mu) * inv * g4.x + b4.x;
    o.y = (v.y - mu) * inv * g4.y + b4.y;
    o.z = (v.z - mu) * inv * g4.z + b4.z;
    o.w = (v.w - mu) * inv * g4.w + b4.w;
    reinterpret_cast<float4*>(out)[(size_t)row * (H_ / 4) + tid] = o;
}

// ---------------- launch ----------------
extern "C" void kernel_launch(void* const* d_in, const int* in_sizes, int n_in,
                              void* d_out, int out_size)
{
    const float* user  = (const float*)d_in[0];
    const float* item  = (const float*)d_in[1];
    const float* mask  = (const float*)d_in[2];
    const void*  indexp =               d_in[3];
    const float* Wq    = (const float*)d_in[4];
    const float* bq    = (const float*)d_in[5];
    const float* Wk    = (const float*)d_in[6];
    const float* bk    = (const float*)d_in[7];
    const float* Wv    = (const float*)d_in[8];
    const float* bv    = (const float*)d_in[9];
    const float* Wd    = (const float*)d_in[10];
    const float* bd    = (const float*)d_in[11];
    const float* lng   = (const float*)d_in[12];
    const float* lnb   = (const float*)d_in[13];
    float* out = (float*)d_out;

    float *xp;
    __half *vhp, *attnhp, *itemhp, *wvhp, *wdhp;
    cudaGetSymbolAddress((void**)&vhp,    g_vh);
    cudaGetSymbolAddress((void**)&attnhp, g_attnh);
    cudaGetSymbolAddress((void**)&xp,     g_x);
    cudaGetSymbolAddress((void**)&itemhp, g_itemh);
    cudaGetSymbolAddress((void**)&wvhp,   g_wvh);
    cudaGetSymbolAddress((void**)&wdhp,   g_wdh);

    cudaFuncSetAttribute(gemm_h_kernel, cudaFuncAttributeMaxDynamicSharedMemorySize, GH_SMEM);

    // (1,2) index normalization
    detect_kernel<<<1, 32>>>((const unsigned int*)indexp);
    convert_kernel<<<(L_ * KK_ + 255) / 256, 256>>>(indexp);

    // (3) fp16 conversions, (4) qproj
    to_half_kernel<<<(ITEM4 + 2 * WQ4 + 255) / 256, 256>>>(item, Wv, Wd);
    qproj_kernel<<<(B_ * H_) / 8, 256>>>(user, Wq, bq);

    // (5) p = Wk^T q
    pk_kernel<<<dim3(H_ / 128, B_), 128>>>(Wk, bk);

    // (6) scores (fp32, from item directly)
    score_kernel<<<BL_ / 8, 256>>>(item);

    // (7) V projection -> fp16
    dim3 gv(H_ / 128, BL_ / 128);      // (4, 128)
    gemm_h_kernel<<<gv, 128, GH_SMEM>>>(itemhp, wvhp, bv, nullptr, nullptr, vhp, 1);

    // (8) gather + softmax + weighted sum -> fp16 attn
    attn_kernel<<<BL_, 128>>>(mask);

    // (9) dense = attn @ Wd^T + bd + item
    gemm_h_kernel<<<gv, 128, GH_SMEM>>>(attnhp, wdhp, bd, item, xp, nullptr, 0);

    // (10) layernorm -> out
    ln_kernel<<<BL_, 128>>>(lng, lnb, out);
}

// round 8
// speedup vs baseline: 3.8790x; 1.0639x over previous
#include <cuda_runtime.h>
#include <cuda_fp16.h>
#include <math.h>
#include <stdint.h>

#define B_  16
#define L_  1024
#define H_  512
#define KK_ 32
#define BL_ (B_ * L_)          // 16384
#define INVSQ 0.04419417382415922f

// ---------------- scratch (no allocations allowed) ----------------
__device__ float  g_q[B_ * H_];
__device__ float  g_p[B_ * H_];            // Wk^T q (pre-scaled)
__device__ float  g_qbk[B_];               // q . bk (pre-scaled)
__device__ float  g_s[B_ * L_];
__device__ __half g_vd[BL_ * H_];          // VD = item @ (Wd Wv)^T, fp16
__device__ __half g_itemh[BL_ * H_];       // fp16 item (GEMM A)
__device__ __half g_wvdh[H_ * H_];         // fp16 Wvd = Wd @ Wv
__device__ float  g_bvd[H_];               // Wd bv + bd
__device__ float  g_zb[H_];                // zero bias (stays 0)
__device__ int    g_index[L_ * KK_];
__device__ int    g_is64;

__device__ __forceinline__ void cp16(uint32_t d, const void* g) {
    asm volatile("cp.async.cg.shared.global [%0], [%1], 16;" :: "r"(d), "l"(g));
}
__device__ __forceinline__ uint32_t smem_u32(const void* p) {
    uint32_t a;
    asm("{ .reg .u64 t; cvta.to.shared.u64 t, %1; cvt.u32.u64 %0, t; }" : "=r"(a) : "l"(p));
    return a;
}
__device__ __forceinline__ void mma_f16(float* d, const uint32_t* a, const uint32_t* b) {
    asm volatile(
        "mma.sync.aligned.m16n8k16.row.col.f32.f16.f16.f32 "
        "{%0,%1,%2,%3}, {%4,%5,%6,%7}, {%8,%9}, {%0,%1,%2,%3};"
        : "+f"(d[0]), "+f"(d[1]), "+f"(d[2]), "+f"(d[3])
        : "r"(a[0]), "r"(a[1]), "r"(a[2]), "r"(a[3]), "r"(b[0]), "r"(b[1]));
}

// ---------------- (1) index dtype detection ----------------
__global__ void detect_kernel(const unsigned int* __restrict__ w) {
    unsigned int any = 0;
    for (int i = threadIdx.x; i < 1024; i += 32)
        any |= w[2 * i + 1];
    #pragma unroll
    for (int o = 16; o; o >>= 1)
        any |= __shfl_xor_sync(0xFFFFFFFFu, any, o);
    if (threadIdx.x == 0) g_is64 = (any == 0u) ? 1 : 0;
}

// ---------------- (2) index normalization ----------------
__global__ void convert_kernel(const void* __restrict__ idx) {
    int i = blockIdx.x * blockDim.x + threadIdx.x;
    if (i >= L_ * KK_) return;
    if (g_is64) g_index[i] = (int)((const long long*)idx)[i];
    else        g_index[i] = ((const int*)idx)[i];
}

// ---------------- (3) fp16 conversion of item ----------------
#define ITEM4 (BL_ * H_ / 4)
__global__ __launch_bounds__(256) void to_half_kernel(const float* __restrict__ item) {
    int i = blockIdx.x * blockDim.x + threadIdx.x;
    if (i >= ITEM4) return;
    float4 v = reinterpret_cast<const float4*>(item)[i];
    uint2 o;
    *reinterpret_cast<__half2*>(&o.x) = __floats2half2_rn(v.x, v.y);
    *reinterpret_cast<__half2*>(&o.y) = __floats2half2_rn(v.z, v.w);
    reinterpret_cast<uint2*>(g_itemh)[i] = o;
}

// ---------------- (4) Wvd = Wd @ Wv  (fp32 compute, fp16 out) ----------------
__global__ __launch_bounds__(256) void wvd_kernel(
    const float* __restrict__ Wd, const float* __restrict__ Wv)
{
    __shared__ float Ad[16][68];   // [j][n]
    __shared__ float Bs[16][68];   // [j][k]
    const int tid = threadIdx.x;
    const int tx = tid & 15, ty = tid >> 4;
    const int bn = blockIdx.y * 64, bk = blockIdx.x * 64;

    float acc[4][4];
    #pragma unroll
    for (int a = 0; a < 4; a++)
        #pragma unroll
        for (int c = 0; c < 4; c++) acc[a][c] = 0.f;

    for (int j0 = 0; j0 < H_; j0 += 16) {
        #pragma unroll
        for (int i = 0; i < 4; i++) {
            int e = tid * 4 + i;                    // 0..1023
            int n = e >> 4, j = e & 15;
            Ad[j][n] = Wd[(size_t)(bn + n) * H_ + j0 + j];
            int j2 = e >> 6, k = e & 63;
            Bs[j2][k] = Wv[(size_t)(j0 + j2) * H_ + bk + k];
        }
        __syncthreads();
        #pragma unroll
        for (int j = 0; j < 16; j++)
            #pragma unroll
            for (int a = 0; a < 4; a++)
                #pragma unroll
                for (int c = 0; c < 4; c++)
                    acc[a][c] += Ad[j][ty * 4 + a] * Bs[j][tx * 4 + c];
        __syncthreads();
    }
    #pragma unroll
    for (int a = 0; a < 4; a++)
        #pragma unroll
        for (int c = 0; c < 4; c++)
            g_wvdh[(size_t)(bn + ty * 4 + a) * H_ + bk + tx * 4 + c] =
                __float2half_rn(acc[a][c]);
}

// ---------------- (5) bvd = Wd bv + bd ----------------
__global__ __launch_bounds__(256) void bvd_kernel(
    const float* __restrict__ Wd, const float* __restrict__ bv,
    const float* __restrict__ bd)
{
    int row  = (blockIdx.x * blockDim.x + threadIdx.x) >> 5;  // 0..511
    int lane = threadIdx.x & 31;
    const float4* w4 = reinterpret_cast<const float4*>(Wd + (size_t)row * H_);
    const float4* b4 = reinterpret_cast<const float4*>(bv);
    float acc = 0.f;
    #pragma unroll
    for (int i = lane; i < H_ / 4; i += 32) {
        float4 w = w4[i], b = b4[i];
        acc += w.x * b.x + w.y * b.y + w.z * b.z + w.w * b.w;
    }
    #pragma unroll
    for (int off = 16; off; off >>= 1)
        acc += __shfl_xor_sync(0xFFFFFFFFu, acc, off);
    if (lane == 0) g_bvd[row] = acc + bd[row];
}

// ---------------- (6) q projection (fp32) ----------------
__global__ __launch_bounds__(256) void qproj_kernel(
    const float* __restrict__ user, const float* __restrict__ Wq,
    const float* __restrict__ bq)
{
    int o    = (blockIdx.x * blockDim.x + threadIdx.x) >> 5;
    int lane = threadIdx.x & 31;
    int b = o >> 9;
    int n = o & 511;
    const float4* u4 = reinterpret_cast<const float4*>(user + (size_t)b * H_);
    const float4* w4 = reinterpret_cast<const float4*>(Wq + (size_t)n * H_);
    float acc = 0.f;
    #pragma unroll
    for (int i = lane; i < H_ / 4; i += 32) {
        float4 a = u4[i], w = w4[i];
        acc += a.x * w.x + a.y * w.y + a.z * w.z + a.w * w.w;
    }
    #pragma unroll
    for (int off = 16; off; off >>= 1)
        acc += __shfl_xor_sync(0xFFFFFFFFu, acc, off);
    if (lane == 0) g_q[o] = acc + bq[n];
}

// ---------------- (7) p[b] = Wk^T q[b] (pre-scaled), qbk[b] = q.bk ----------------
__global__ __launch_bounds__(128) void pk_kernel(
    const float* __restrict__ Wk, const float* __restrict__ bk)
{
    const int b  = blockIdx.y;
    const int j  = blockIdx.x * 128 + threadIdx.x;
    const int tid = threadIdx.x;
    __shared__ float qs[H_];
    __shared__ float red[128];
    for (int i = tid; i < H_; i += 128) qs[i] = g_q[b * H_ + i];
    __syncthreads();

    float acc = 0.f;
    #pragma unroll 8
    for (int i = 0; i < H_; i++)
        acc += Wk[(size_t)i * H_ + j] * qs[i];
    g_p[b * H_ + j] = acc * INVSQ;

    if (blockIdx.x == 0) {
        float a = 0.f;
        for (int i = tid; i < H_; i += 128) a += qs[i] * bk[i];
        red[tid] = a;
        __syncthreads();
        #pragma unroll
        for (int s = 64; s; s >>= 1) {
            if (tid < s) red[tid] += red[tid + s];
            __syncthreads();
        }
        if (tid == 0) g_qbk[b] = red[0] * INVSQ;
    }
}

// ---------------- (8) scores: s[b,l] = p[b].item[b,l] + qbk[b] ----------------
__global__ __launch_bounds__(256) void score_kernel(const float* __restrict__ item) {
    int w    = (blockIdx.x * blockDim.x + threadIdx.x) >> 5;
    int lane = threadIdx.x & 31;
    int b = w >> 10;
    const float4* ir = reinterpret_cast<const float4*>(item + (size_t)w * H_);
    const float4* pr = reinterpret_cast<const float4*>(g_p + (size_t)b * H_);
    float acc = 0.f;
    #pragma unroll
    for (int i = lane; i < H_ / 4; i += 32) {
        float4 a = ir[i], p = pr[i];
        acc += a.x * p.x + a.y * p.y + a.z * p.z + a.w * p.w;
    }
    #pragma unroll
    for (int off = 16; off; off >>= 1)
        acc += __shfl_xor_sync(0xFFFFFFFFu, acc, off);
    if (lane == 0) g_s[w] = acc + g_qbk[b];
}

// ================= (9) fp16 mma.sync GEMM: VD = item_h @ Wvd^T ================
// CTA 128x128, 4 warps (warp 64x64), BK=32, m16n8k16, 3-stage cp.async ring.
#define GH_STRIDE 40
#define GH_TILE   (128 * GH_STRIDE)
#define GH_SLOT   (2 * GH_TILE)
#define GH_SMEM   (3 * GH_SLOT * 2)            // 61440 bytes

__global__ void __launch_bounds__(128) gemm_h_kernel(
    const __half* __restrict__ A, const __half* __restrict__ W,
    const float* __restrict__ bias, __half* __restrict__ Ch)
{
    extern __shared__ __half smh[];

    const int tid  = threadIdx.x;
    const int lane = tid & 31;
    const int warp = tid >> 5;
    const int wm   = (warp & 1) * 64;
    const int wn   = (warp >> 1) * 64;
    const int g    = lane >> 2;
    const int t    = lane & 3;
    const int bm   = blockIdx.y * 128;
    const int bn   = blockIdx.x * 128;

    const int lrow = tid >> 2;
    const int lc   = tid & 3;

    const __half* Abase = A + (size_t)bm * H_ + lc * 8;
    const __half* Bbase = W + (size_t)bn * H_ + lc * 8;

    float acc[4][8][4];
    #pragma unroll
    for (int mi = 0; mi < 4; mi++)
        #pragma unroll
        for (int ni = 0; ni < 8; ni++)
            #pragma unroll
            for (int r = 0; r < 4; r++) acc[mi][ni][r] = 0.f;

    const uint32_t smb = smem_u32(smh);
    const int NST = H_ / 32;   // 16

    #pragma unroll
    for (int p = 0; p < 2; p++) {
        const uint32_t ab = smb + (uint32_t)(p * GH_SLOT) * 2;
        const uint32_t bb = ab + GH_TILE * 2;
        const int k0 = p * 32;
        #pragma unroll
        for (int i = 0; i < 4; i++) {
            int row = lrow + i * 32;
            uint32_t off = (uint32_t)(row * 80 + lc * 16);
            cp16(ab + off, Abase + (size_t)row * H_ + k0);
            cp16(bb + off, Bbase + (size_t)row * H_ + k0);
        }
        asm volatile("cp.async.commit_group;" ::: "memory");
    }

    for (int s = 0; s < NST; s++) {
        if (s < NST - 1) asm volatile("cp.async.wait_group 1;" ::: "memory");
        else             asm volatile("cp.async.wait_group 0;" ::: "memory");
        __syncthreads();

        if (s + 2 < NST) {
            const int slot = (s + 2) % 3;
            const uint32_t ab = smb + (uint32_t)(slot * GH_SLOT) * 2;
            const uint32_t bb = ab + GH_TILE * 2;
            const int k0 = (s + 2) * 32;
            #pragma unroll
            for (int i = 0; i < 4; i++) {
                int row = lrow + i * 32;
                uint32_t off = (uint32_t)(row * 80 + lc * 16);
                cp16(ab + off, Abase + (size_t)row * H_ + k0);
                cp16(bb + off, Bbase + (size_t)row * H_ + k0);
            }
            asm volatile("cp.async.commit_group;" ::: "memory");
        }

        const __half* slotp = smh + (s % 3) * GH_SLOT;
        const uint32_t* Au = reinterpret_cast<const uint32_t*>(slotp);
        const uint32_t* Bu = reinterpret_cast<const uint32_t*>(slotp + GH_TILE);
        #pragma unroll
        for (int kk = 0; kk < 2; kk++) {
            const int kw = kk * 8;
            uint32_t af[4][4], bf[8][2];
            #pragma unroll
            for (int mi = 0; mi < 4; mi++) {
                int row = wm + mi * 16 + g;
                af[mi][0] = Au[row * 20 + kw + t];
                af[mi][1] = Au[(row + 8) * 20 + kw + t];
                af[mi][2] = Au[row * 20 + kw + t + 4];
                af[mi][3] = Au[(row + 8) * 20 + kw + t + 4];
            }
            #pragma unroll
            for (int ni = 0; ni < 8; ni++) {
                int col = wn + ni * 8 + g;
                bf[ni][0] = Bu[col * 20 + kw + t];
                bf[ni][1] = Bu[col * 20 + kw + t + 4];
            }
            #pragma unroll
            for (int mi = 0; mi < 4; mi++)
                #pragma unroll
                for (int ni = 0; ni < 8; ni++)
                    mma_f16(acc[mi][ni], af[mi], bf[ni]);
        }
    }

    // ---- epilogue: fp16 out (+bias) ----
    #pragma unroll
    for (int mi = 0; mi < 4; mi++) {
        const int m0 = bm + wm + mi * 16 + g;
        #pragma unroll
        for (int ni = 0; ni < 8; ni++) {
            const int n = bn + wn + ni * 8 + 2 * t;
            float2 bs = *reinterpret_cast<const float2*>(bias + n);
            *reinterpret_cast<__half2*>(Ch + (size_t)m0 * H_ + n) =
                __floats2half2_rn(acc[mi][ni][0] + bs.x, acc[mi][ni][1] + bs.y);
            *reinterpret_cast<__half2*>(Ch + (size_t)(m0 + 8) * H_ + n) =
                __floats2half2_rn(acc[mi][ni][2] + bs.x, acc[mi][ni][3] + bs.y);
        }
    }
}

// ------- (10) fused: gather + softmax + weighted VD sum + bvd + residual + LN ----
__global__ __launch_bounds__(128) void attn_ln_kernel(
    const float* __restrict__ mask, const float* __restrict__ item,
    const float* __restrict__ gma, const float* __restrict__ bta,
    float* __restrict__ out)
{
    __shared__ float wsh[KK_];
    __shared__ int   ish[KK_];
    __shared__ float sh[8];
    const int bl  = blockIdx.x;
    const int b   = bl >> 10;
    const int l   = bl & 1023;
    const int tid = threadIdx.x;

    if (tid < KK_) {
        int   idx = g_index[l * KK_ + tid];
        float s   = g_s[b * L_ + idx] + mask[(size_t)bl * KK_ + tid];
        ish[tid]  = idx;
        float mx = s;
        #pragma unroll
        for (int o = 16; o; o >>= 1)
            mx = fmaxf(mx, __shfl_xor_sync(0xFFFFFFFFu, mx, o));
        float e = expf(s - mx);
        float sum = e;
        #pragma unroll
        for (int o = 16; o; o >>= 1)
            sum += __shfl_xor_sync(0xFFFFFFFFu, sum, o);
        wsh[tid] = e / sum;
    }
    __syncthreads();

    const uint2* vd = reinterpret_cast<const uint2*>(g_vd);
    float4 acc = make_float4(0.f, 0.f, 0.f, 0.f);
    #pragma unroll 8
    for (int k = 0; k < KK_; k++) {
        float wk = wsh[k];
        uint2 u  = vd[((size_t)(b * L_ + ish[k])) * (H_ / 4) + tid];
        float2 f0 = __half22float2(*reinterpret_cast<__half2*>(&u.x));
        float2 f1 = __half22float2(*reinterpret_cast<__half2*>(&u.y));
        acc.x += wk * f0.x;
        acc.y += wk * f0.y;
        acc.z += wk * f1.x;
        acc.w += wk * f1.y;
    }
    // x = acc + bvd + item
    float4 it = reinterpret_cast<const float4*>(item)[(size_t)bl * (H_ / 4) + tid];
    float4 bv = reinterpret_cast<const float4*>(g_bvd)[tid];
    float4 v;
    v.x = acc.x + bv.x + it.x;
    v.y = acc.y + bv.y + it.y;
    v.z = acc.z + bv.z + it.z;
    v.w = acc.w + bv.w + it.w;

    // LayerNorm over 512
    float s  = v.x + v.y + v.z + v.w;
    float ss = v.x * v.x + v.y * v.y + v.z * v.z + v.w * v.w;
    #pragma unroll
    for (int o = 16; o; o >>= 1) {
        s  += __shfl_xor_sync(0xFFFFFFFFu, s, o);
        ss += __shfl_xor_sync(0xFFFFFFFFu, ss, o);
    }
    int wid = tid >> 5, lane = tid & 31;
    if (lane == 0) { sh[wid] = s; sh[4 + wid] = ss; }
    __syncthreads();
    if (tid == 0) {
        float S  = sh[0] + sh[1] + sh[2] + sh[3];
        float SS = sh[4] + sh[5] + sh[6] + sh[7];
        sh[0] = S; sh[1] = SS;
    }
    __syncthreads();
    float mu  = sh[0] * (1.f / 512.f);
    float var = sh[1] * (1.f / 512.f) - mu * mu;
    float inv = rsqrtf(var + 1e-12f);

    float4 g4 = reinterpret_cast<const float4*>(gma)[tid];
    float4 b4 = reinterpret_cast<const float4*>(bta)[tid];
    float4 o;
    o.x = (v.x - mu) * inv * g4.x + b4.x;
    o.y = (v.y - mu) * inv * g4.y + b4.y;
    o.z = (v.z - mu) * inv * g4.z + b4.z;
    o.w = (v.w - mu) * inv * g4.w + b4.w;
    reinterpret_cast<float4*>(out)[(size_t)bl * (H_ / 4) + tid] = o;
}

// ---------------- launch ----------------
extern "C" void kernel_launch(void* const* d_in, const int* in_sizes, int n_in,
                              void* d_out, int out_size)
{
    const float* user  = (const float*)d_in[0];
    const float* item  = (const float*)d_in[1];
    const float* mask  = (const float*)d_in[2];
    const void*  indexp =               d_in[3];
    const float* Wq    = (const float*)d_in[4];
    const float* bq    = (const float*)d_in[5];
    const float* Wk    = (const float*)d_in[6];
    const float* bk    = (const float*)d_in[7];
    const float* Wv    = (const float*)d_in[8];
    const float* bv    = (const float*)d_in[9];
    const float* Wd    = (const float*)d_in[10];
    const float* bd    = (const float*)d_in[11];
    const float* lng   = (const float*)d_in[12];
    const float* lnb   = (const float*)d_in[13];
    float* out = (float*)d_out;

    __half *vdp, *itemhp, *wvdhp;
    float  *zbp;
    cudaGetSymbolAddress((void**)&vdp,    g_vd);
    cudaGetSymbolAddress((void**)&itemhp, g_itemh);
    cudaGetSymbolAddress((void**)&wvdhp,  g_wvdh);
    cudaGetSymbolAddress((void**)&zbp,    g_zb);

    cudaFuncSetAttribute(gemm_h_kernel, cudaFuncAttributeMaxDynamicSharedMemorySize, GH_SMEM);

    // (1,2) index normalization
    detect_kernel<<<1, 32>>>((const unsigned int*)indexp);
    convert_kernel<<<(L_ * KK_ + 255) / 256, 256>>>(indexp);

    // (3) item -> fp16, (4) Wvd = Wd@Wv, (5) bvd, (6) qproj
    to_half_kernel<<<(ITEM4 + 255) / 256, 256>>>(item);
    wvd_kernel<<<dim3(8, 8), 256>>>(Wd, Wv);
    bvd_kernel<<<(H_ * 32 + 255) / 256, 256>>>(Wd, bv, bd);
    qproj_kernel<<<(B_ * H_) / 8, 256>>>(user, Wq, bq);

    // (7) p = Wk^T q
    pk_kernel<<<dim3(H_ / 128, B_), 128>>>(Wk, bk);

    // (8) scores (fp32, from item directly)
    score_kernel<<<BL_ / 8, 256>>>(item);

    // (9) single GEMM: VD = item_h @ Wvd^T (zero bias)
    dim3 gv(H_ / 128, BL_ / 128);      // (4, 128)
    gemm_h_kernel<<<gv, 128, GH_SMEM>>>(itemhp, wvdhp, zbp, vdp);

    // (10) fused gather + softmax + bvd + residual + LN -> out
    attn_ln_kernel<<<BL_, 128>>>(mask, item, lng, lnb, out);
}

// round 9
// speedup vs baseline: 4.2290x; 1.0902x over previous
#include <cuda_runtime.h>
#include <cuda_fp16.h>
#include <math.h>
#include <stdint.h>

#define B_  16
#define L_  1024
#define H_  512
#define KK_ 32
#define BL_ (B_ * L_)          // 16384
#define INVSQ 0.04419417382415922f
#define WSPLIT 8

// ---------------- scratch (no allocations allowed) ----------------
__device__ float  g_q[B_ * H_];
__device__ float  g_p[B_ * H_];            // Wk^T q (pre-scaled)
__device__ float  g_qbk[B_];               // q . bk (pre-scaled)
__device__ float  g_s[B_ * L_];
__device__ __half g_vd[BL_ * H_];          // VD = item @ (Wd Wv)^T, fp16
__device__ __half g_itemh[BL_ * H_];       // fp16 item (GEMM A)
__device__ __half g_wvdh[H_ * H_];         // fp16 Wvd = Wd @ Wv
__device__ float  g_wvdp[WSPLIT * H_ * H_]; // split-K partials
__device__ float  g_bvd[H_];               // Wd bv + bd
__device__ float  g_zb[H_];                // zero bias (stays 0)
__device__ int    g_index[L_ * KK_];
__device__ int    g_is64;

__device__ __forceinline__ void cp16(uint32_t d, const void* g) {
    asm volatile("cp.async.cg.shared.global [%0], [%1], 16;" :: "r"(d), "l"(g));
}
__device__ __forceinline__ uint32_t smem_u32(const void* p) {
    uint32_t a;
    asm("{ .reg .u64 t; cvta.to.shared.u64 t, %1; cvt.u32.u64 %0, t; }" : "=r"(a) : "l"(p));
    return a;
}
__device__ __forceinline__ void mma_f16(float* d, const uint32_t* a, const uint32_t* b) {
    asm volatile(
        "mma.sync.aligned.m16n8k16.row.col.f32.f16.f16.f32 "
        "{%0,%1,%2,%3}, {%4,%5,%6,%7}, {%8,%9}, {%0,%1,%2,%3};"
        : "+f"(d[0]), "+f"(d[1]), "+f"(d[2]), "+f"(d[3])
        : "r"(a[0]), "r"(a[1]), "r"(a[2]), "r"(a[3]), "r"(b[0]), "r"(b[1]));
}

// ---------------- (1) index dtype detection ----------------
__global__ void detect_kernel(const unsigned int* __restrict__ w) {
    unsigned int any = 0;
    for (int i = threadIdx.x; i < 1024; i += 32)
        any |= w[2 * i + 1];
    #pragma unroll
    for (int o = 16; o; o >>= 1)
        any |= __shfl_xor_sync(0xFFFFFFFFu, any, o);
    if (threadIdx.x == 0) g_is64 = (any == 0u) ? 1 : 0;
}

// ---------------- (2) index normalization ----------------
__global__ void convert_kernel(const void* __restrict__ idx) {
    int i = blockIdx.x * blockDim.x + threadIdx.x;
    if (i >= L_ * KK_) return;
    if (g_is64) g_index[i] = (int)((const long long*)idx)[i];
    else        g_index[i] = ((const int*)idx)[i];
}

// ---------------- (3) fp16 conversion of item ----------------
#define ITEM4 (BL_ * H_ / 4)
__global__ __launch_bounds__(256) void to_half_kernel(const float* __restrict__ item) {
    int i = blockIdx.x * blockDim.x + threadIdx.x;
    if (i >= ITEM4) return;
    float4 v = reinterpret_cast<const float4*>(item)[i];
    uint2 o;
    *reinterpret_cast<__half2*>(&o.x) = __floats2half2_rn(v.x, v.y);
    *reinterpret_cast<__half2*>(&o.y) = __floats2half2_rn(v.z, v.w);
    reinterpret_cast<uint2*>(g_itemh)[i] = o;
}

// ---------------- (4a) Wvd partials: split-K over j ----------------
// partial[z][r,c] = sum_{j in slice z} Wd[r,j] * Wv[j,c]
__global__ __launch_bounds__(256) void wvd_kernel(
    const float* __restrict__ Wd, const float* __restrict__ Wv)
{
    __shared__ float Ad[16][68];   // [j][r]
    __shared__ float Bs[16][68];   // [j][c]
    const int tid = threadIdx.x;
    const int tx = tid & 15, ty = tid >> 4;
    const int bn = blockIdx.y * 64, bk = blockIdx.x * 64;
    const int jbase = blockIdx.z * (H_ / WSPLIT);   // 64-j slice

    float acc[4][4];
    #pragma unroll
    for (int a = 0; a < 4; a++)
        #pragma unroll
        for (int c = 0; c < 4; c++) acc[a][c] = 0.f;

    for (int j0 = jbase; j0 < jbase + H_ / WSPLIT; j0 += 16) {
        #pragma unroll
        for (int i = 0; i < 4; i++) {
            int e = tid * 4 + i;                    // 0..1023
            int n = e >> 4, j = e & 15;
            Ad[j][n] = Wd[(size_t)(bn + n) * H_ + j0 + j];
            int j2 = e >> 6, k = e & 63;
            Bs[j2][k] = Wv[(size_t)(j0 + j2) * H_ + bk + k];
        }
        __syncthreads();
        #pragma unroll
        for (int j = 0; j < 16; j++)
            #pragma unroll
            for (int a = 0; a < 4; a++)
                #pragma unroll
                for (int c = 0; c < 4; c++)
                    acc[a][c] += Ad[j][ty * 4 + a] * Bs[j][tx * 4 + c];
        __syncthreads();
    }
    float* dst = g_wvdp + (size_t)blockIdx.z * H_ * H_;
    #pragma unroll
    for (int a = 0; a < 4; a++)
        #pragma unroll
        for (int c = 0; c < 4; c++)
            dst[(size_t)(bn + ty * 4 + a) * H_ + bk + tx * 4 + c] = acc[a][c];
}

// ---------------- (4b) reduce partials -> fp16 Wvd ----------------
__global__ __launch_bounds__(256) void wvd_reduce_kernel() {
    int i = blockIdx.x * blockDim.x + threadIdx.x;   // float4 index, 65536 total
    if (i >= H_ * H_ / 4) return;
    float4 s = reinterpret_cast<const float4*>(g_wvdp)[i];
    #pragma unroll
    for (int z = 1; z < WSPLIT; z++) {
        float4 p = reinterpret_cast<const float4*>(g_wvdp + (size_t)z * H_ * H_)[i];
        s.x += p.x; s.y += p.y; s.z += p.z; s.w += p.w;
    }
    uint2 o;
    *reinterpret_cast<__half2*>(&o.x) = __floats2half2_rn(s.x, s.y);
    *reinterpret_cast<__half2*>(&o.y) = __floats2half2_rn(s.z, s.w);
    reinterpret_cast<uint2*>(g_wvdh)[i] = o;
}

// ---------------- (5) bvd = Wd bv + bd ----------------
__global__ __launch_bounds__(256) void bvd_kernel(
    const float* __restrict__ Wd, const float* __restrict__ bv,
    const float* __restrict__ bd)
{
    int row  = (blockIdx.x * blockDim.x + threadIdx.x) >> 5;  // 0..511
    int lane = threadIdx.x & 31;
    const float4* w4 = reinterpret_cast<const float4*>(Wd + (size_t)row * H_);
    const float4* b4 = reinterpret_cast<const float4*>(bv);
    float acc = 0.f;
    #pragma unroll
    for (int i = lane; i < H_ / 4; i += 32) {
        float4 w = w4[i], b = b4[i];
        acc += w.x * b.x + w.y * b.y + w.z * b.z + w.w * b.w;
    }
    #pragma unroll
    for (int off = 16; off; off >>= 1)
        acc += __shfl_xor_sync(0xFFFFFFFFu, acc, off);
    if (lane == 0) g_bvd[row] = acc + bd[row];
}

// ---------------- (6) q projection (fp32) ----------------
__global__ __launch_bounds__(256) void qproj_kernel(
    const float* __restrict__ user, const float* __restrict__ Wq,
    const float* __restrict__ bq)
{
    int o    = (blockIdx.x * blockDim.x + threadIdx.x) >> 5;
    int lane = threadIdx.x & 31;
    int b = o >> 9;
    int n = o & 511;
    const float4* u4 = reinterpret_cast<const float4*>(user + (size_t)b * H_);
    const float4* w4 = reinterpret_cast<const float4*>(Wq + (size_t)n * H_);
    float acc = 0.f;
    #pragma unroll
    for (int i = lane; i < H_ / 4; i += 32) {
        float4 a = u4[i], w = w4[i];
        acc += a.x * w.x + a.y * w.y + a.z * w.z + a.w * w.w;
    }
    #pragma unroll
    for (int off = 16; off; off >>= 1)
        acc += __shfl_xor_sync(0xFFFFFFFFu, acc, off);
    if (lane == 0) g_q[o] = acc + bq[n];
}

// ---------------- (7) p[b] = Wk^T q[b] (pre-scaled), qbk[b] = q.bk ----------------
__global__ __launch_bounds__(128) void pk_kernel(
    const float* __restrict__ Wk, const float* __restrict__ bk)
{
    const int b  = blockIdx.y;
    const int j  = blockIdx.x * 128 + threadIdx.x;
    const int tid = threadIdx.x;
    __shared__ float qs[H_];
    __shared__ float red[128];
    for (int i = tid; i < H_; i += 128) qs[i] = g_q[b * H_ + i];
    __syncthreads();

    float acc = 0.f;
    #pragma unroll 8
    for (int i = 0; i < H_; i++)
        acc += Wk[(size_t)i * H_ + j] * qs[i];
    g_p[b * H_ + j] = acc * INVSQ;

    if (blockIdx.x == 0) {
        float a = 0.f;
        for (int i = tid; i < H_; i += 128) a += qs[i] * bk[i];
        red[tid] = a;
        __syncthreads();
        #pragma unroll
        for (int s = 64; s; s >>= 1) {
            if (tid < s) red[tid] += red[tid + s];
            __syncthreads();
        }
        if (tid == 0) g_qbk[b] = red[0] * INVSQ;
    }
}

// ---------------- (8) scores: s[b,l] = p[b].item_h[b,l] + qbk[b] ----------------
__global__ __launch_bounds__(256) void score_kernel() {
    int w    = (blockIdx.x * blockDim.x + threadIdx.x) >> 5;
    int lane = threadIdx.x & 31;
    int b = w >> 10;
    const uint2*  ir = reinterpret_cast<const uint2*>(g_itemh + (size_t)w * H_);
    const float4* pr = reinterpret_cast<const float4*>(g_p + (size_t)b * H_);
    float acc = 0.f;
    #pragma unroll
    for (int i = lane; i < H_ / 4; i += 32) {
        uint2 u = ir[i];
        float2 f0 = __half22float2(*reinterpret_cast<__half2*>(&u.x));
        float2 f1 = __half22float2(*reinterpret_cast<__half2*>(&u.y));
        float4 p = pr[i];
        acc += f0.x * p.x + f0.y * p.y + f1.x * p.z + f1.y * p.w;
    }
    #pragma unroll
    for (int off = 16; off; off >>= 1)
        acc += __shfl_xor_sync(0xFFFFFFFFu, acc, off);
    if (lane == 0) g_s[w] = acc + g_qbk[b];
}

// ================= (9) fp16 mma.sync GEMM: VD = item_h @ Wvd^T ================
// CTA 128x128, 4 warps (warp 64x64), BK=32, m16n8k16, 3-stage cp.async ring.
#define GH_STRIDE 40
#define GH_TILE   (128 * GH_STRIDE)
#define GH_SLOT   (2 * GH_TILE)
#define GH_SMEM   (3 * GH_SLOT * 2)            // 61440 bytes

__global__ void __launch_bounds__(128) gemm_h_kernel(
    const __half* __restrict__ A, const __half* __restrict__ W,
    const float* __restrict__ bias, __half* __restrict__ Ch)
{
    extern __shared__ __half smh[];

    const int tid  = threadIdx.x;
    const int lane = tid & 31;
    const int warp = tid >> 5;
    const int wm   = (warp & 1) * 64;
    const int wn   = (warp >> 1) * 64;
    const int g    = lane >> 2;
    const int t    = lane & 3;
    const int bm   = blockIdx.y * 128;
    const int bn   = blockIdx.x * 128;

    const int lrow = tid >> 2;
    const int lc   = tid & 3;

    const __half* Abase = A + (size_t)bm * H_ + lc * 8;
    const __half* Bbase = W + (size_t)bn * H_ + lc * 8;

    float acc[4][8][4];
    #pragma unroll
    for (int mi = 0; mi < 4; mi++)
        #pragma unroll
        for (int ni = 0; ni < 8; ni++)
            #pragma unroll
            for (int r = 0; r < 4; r++) acc[mi][ni][r] = 0.f;

    const uint32_t smb = smem_u32(smh);
    const int NST = H_ / 32;   // 16

    #pragma unroll
    for (int p = 0; p < 2; p++) {
        const uint32_t ab = smb + (uint32_t)(p * GH_SLOT) * 2;
        const uint32_t bb = ab + GH_TILE * 2;
        const int k0 = p * 32;
        #pragma unroll
        for (int i = 0; i < 4; i++) {
            int row = lrow + i * 32;
            uint32_t off = (uint32_t)(row * 80 + lc * 16);
            cp16(ab + off, Abase + (size_t)row * H_ + k0);
            cp16(bb + off, Bbase + (size_t)row * H_ + k0);
        }
        asm volatile("cp.async.commit_group;" ::: "memory");
    }

    for (int s = 0; s < NST; s++) {
        if (s < NST - 1) asm volatile("cp.async.wait_group 1;" ::: "memory");
        else             asm volatile("cp.async.wait_group 0;" ::: "memory");
        __syncthreads();

        if (s + 2 < NST) {
            const int slot = (s + 2) % 3;
            const uint32_t ab = smb + (uint32_t)(slot * GH_SLOT) * 2;
            const uint32_t bb = ab + GH_TILE * 2;
            const int k0 = (s + 2) * 32;
            #pragma unroll
            for (int i = 0; i < 4; i++) {
                int row = lrow + i * 32;
                uint32_t off = (uint32_t)(row * 80 + lc * 16);
                cp16(ab + off, Abase + (size_t)row * H_ + k0);
                cp16(bb + off, Bbase + (size_t)row * H_ + k0);
            }
            asm volatile("cp.async.commit_group;" ::: "memory");
        }

        const __half* slotp = smh + (s % 3) * GH_SLOT;
        const uint32_t* Au = reinterpret_cast<const uint32_t*>(slotp);
        const uint32_t* Bu = reinterpret_cast<const uint32_t*>(slotp + GH_TILE);
        #pragma unroll
        for (int kk = 0; kk < 2; kk++) {
            const int kw = kk * 8;
            uint32_t af[4][4], bf[8][2];
            #pragma unroll
            for (int mi = 0; mi < 4; mi++) {
                int row = wm + mi * 16 + g;
                af[mi][0] = Au[row * 20 + kw + t];
                af[mi][1] = Au[(row + 8) * 20 + kw + t];
                af[mi][2] = Au[row * 20 + kw + t + 4];
                af[mi][3] = Au[(row + 8) * 20 + kw + t + 4];
            }
            #pragma unroll
            for (int ni = 0; ni < 8; ni++) {
                int col = wn + ni * 8 + g;
                bf[ni][0] = Bu[col * 20 + kw + t];
                bf[ni][1] = Bu[col * 20 + kw + t + 4];
            }
            #pragma unroll
            for (int mi = 0; mi < 4; mi++)
                #pragma unroll
                for (int ni = 0; ni < 8; ni++)
                    mma_f16(acc[mi][ni], af[mi], bf[ni]);
        }
    }

    // ---- epilogue: fp16 out (+bias) ----
    #pragma unroll
    for (int mi = 0; mi < 4; mi++) {
        const int m0 = bm + wm + mi * 16 + g;
        #pragma unroll
        for (int ni = 0; ni < 8; ni++) {
            const int n = bn + wn + ni * 8 + 2 * t;
            float2 bs = *reinterpret_cast<const float2*>(bias + n);
            *reinterpret_cast<__half2*>(Ch + (size_t)m0 * H_ + n) =
                __floats2half2_rn(acc[mi][ni][0] + bs.x, acc[mi][ni][1] + bs.y);
            *reinterpret_cast<__half2*>(Ch + (size_t)(m0 + 8) * H_ + n) =
                __floats2half2_rn(acc[mi][ni][2] + bs.x, acc[mi][ni][3] + bs.y);
        }
    }
}

// ------- (10) fused: gather + softmax + weighted VD sum + bvd + residual + LN ----
__global__ __launch_bounds__(128) void attn_ln_kernel(
    const float* __restrict__ mask, const float* __restrict__ item,
    const float* __restrict__ gma, const float* __restrict__ bta,
    float* __restrict__ out)
{
    __shared__ float wsh[KK_];
    __shared__ int   ish[KK_];
    __shared__ float sh[8];
    const int bl  = blockIdx.x;
    const int b   = bl >> 10;
    const int l   = bl & 1023;
    const int tid = threadIdx.x;

    if (tid < KK_) {
        int   idx = g_index[l * KK_ + tid];
        float s   = g_s[b * L_ + idx] + mask[(size_t)bl * KK_ + tid];
        ish[tid]  = idx;
        float mx = s;
        #pragma unroll
        for (int o = 16; o; o >>= 1)
            mx = fmaxf(mx, __shfl_xor_sync(0xFFFFFFFFu, mx, o));
        float e = expf(s - mx);
        float sum = e;
        #pragma unroll
        for (int o = 16; o; o >>= 1)
            sum += __shfl_xor_sync(0xFFFFFFFFu, sum, o);
        wsh[tid] = e / sum;
    }
    __syncthreads();

    const uint2* vd = reinterpret_cast<const uint2*>(g_vd);
    float4 acc = make_float4(0.f, 0.f, 0.f, 0.f);
    #pragma unroll 8
    for (int k = 0; k < KK_; k++) {
        float wk = wsh[k];
        uint2 u  = vd[((size_t)(b * L_ + ish[k])) * (H_ / 4) + tid];
        float2 f0 = __half22float2(*reinterpret_cast<__half2*>(&u.x));
        float2 f1 = __half22float2(*reinterpret_cast<__half2*>(&u.y));
        acc.x += wk * f0.x;
        acc.y += wk * f0.y;
        acc.z += wk * f1.x;
        acc.w += wk * f1.y;
    }
    // x = acc + bvd + item
    float4 it = reinterpret_cast<const float4*>(item)[(size_t)bl * (H_ / 4) + tid];
    float4 bv = reinterpret_cast<const float4*>(g_bvd)[tid];
    float4 v;
    v.x = acc.x + bv.x + it.x;
    v.y = acc.y + bv.y + it.y;
    v.z = acc.z + bv.z + it.z;
    v.w = acc.w + bv.w + it.w;

    // LayerNorm over 512
    float s  = v.x + v.y + v.z + v.w;
    float ss = v.x * v.x + v.y * v.y + v.z * v.z + v.w * v.w;
    #pragma unroll
    for (int o = 16; o; o >>= 1) {
        s  += __shfl_xor_sync(0xFFFFFFFFu, s, o);
        ss += __shfl_xor_sync(0xFFFFFFFFu, ss, o);
    }
    int wid = tid >> 5, lane = tid & 31;
    if (lane == 0) { sh[wid] = s; sh[4 + wid] = ss; }
    __syncthreads();
    if (tid == 0) {
        float S  = sh[0] + sh[1] + sh[2] + sh[3];
        float SS = sh[4] + sh[5] + sh[6] + sh[7];
        sh[0] = S; sh[1] = SS;
    }
    __syncthreads();
    float mu  = sh[0] * (1.f / 512.f);
    float var = sh[1] * (1.f / 512.f) - mu * mu;
    float inv = rsqrtf(var + 1e-12f);

    float4 g4 = reinterpret_cast<const float4*>(gma)[tid];
    float4 b4 = reinterpret_cast<const float4*>(bta)[tid];
    float4 o;
    o.x = (v.x - mu) * inv * g4.x + b4.x;
    o.y = (v.y - mu) * inv * g4.y + b4.y;
    o.z = (v.z - mu) * inv * g4.z + b4.z;
    o.w = (v.w - mu) * inv * g4.w + b4.w;
    reinterpret_cast<float4*>(out)[(size_t)bl * (H_ / 4) + tid] = o;
}

// ---------------- launch ----------------
extern "C" void kernel_launch(void* const* d_in, const int* in_sizes, int n_in,
                              void* d_out, int out_size)
{
    const float* user  = (const float*)d_in[0];
    const float* item  = (const float*)d_in[1];
    const float* mask  = (const float*)d_in[2];
    const void*  indexp =               d_in[3];
    const float* Wq    = (const float*)d_in[4];
    const float* bq    = (const float*)d_in[5];
    const float* Wk    = (const float*)d_in[6];
    const float* bk    = (const float*)d_in[7];
    const float* Wv    = (const float*)d_in[8];
    const float* bv    = (const float*)d_in[9];
    const float* Wd    = (const float*)d_in[10];
    const float* bd    = (const float*)d_in[11];
    const float* lng   = (const float*)d_in[12];
    const float* lnb   = (const float*)d_in[13];
    float* out = (float*)d_out;

    __half *vdp, *itemhp, *wvdhp;
    float  *zbp;
    cudaGetSymbolAddress((void**)&vdp,    g_vd);
    cudaGetSymbolAddress((void**)&itemhp, g_itemh);
    cudaGetSymbolAddress((void**)&wvdhp,  g_wvdh);
    cudaGetSymbolAddress((void**)&zbp,    g_zb);

    cudaFuncSetAttribute(gemm_h_kernel, cudaFuncAttributeMaxDynamicSharedMemorySize, GH_SMEM);

    // (1,2) index normalization
    detect_kernel<<<1, 32>>>((const unsigned int*)indexp);
    convert_kernel<<<(L_ * KK_ + 255) / 256, 256>>>(indexp);

    // (3) item -> fp16, (4) Wvd split-K + reduce, (5) bvd, (6) qproj
    to_half_kernel<<<(ITEM4 + 255) / 256, 256>>>(item);
    wvd_kernel<<<dim3(8, 8, WSPLIT), 256>>>(Wd, Wv);
    wvd_reduce_kernel<<<(H_ * H_ / 4 + 255) / 256, 256>>>();
    bvd_kernel<<<(H_ * 32 + 255) / 256, 256>>>(Wd, bv, bd);
    qproj_kernel<<<(B_ * H_) / 8, 256>>>(user, Wq, bq);

    // (7) p = Wk^T q
    pk_kernel<<<dim3(H_ / 128, B_), 128>>>(Wk, bk);

    // (8) scores (fp32 accum over fp16 item)
    score_kernel<<<BL_ / 8, 256>>>();

    // (9) single GEMM: VD = item_h @ Wvd^T (zero bias)
    dim3 gv(H_ / 128, BL_ / 128);      // (4, 128)
    gemm_h_kernel<<<gv, 128, GH_SMEM>>>(itemhp, wvdhp, zbp, vdp);

    // (10) fused gather + softmax + bvd + residual + LN -> out
    attn_ln_kernel<<<BL_, 128>>>(mask, item, lng, lnb, out);
}